// round 6
// baseline (speedup 1.0000x reference)
#include <cuda_runtime.h>
#include <math.h>

// Problem constants
#define BB 16
#define SS 512
#define DM 256
#define HH 8
#define DKV 32
#define CTXW 288   // DV*(H+1)
#define EPS 1e-5f

// -------- scratch (device globals; no allocation allowed) --------
__device__ float g_Q[BB * SS * DM];
__device__ float g_K[BB * SS * DM];
__device__ float g_V[BB * SS * DM];
__device__ float g_attn[(long)BB * HH * SS * SS];   // 134 MB
__device__ float g_vp2[BB * SS * DKV];
__device__ float g_ctx[BB * SS * CTXW];
__device__ float g_fc[BB * SS * DM];

// ---- packed f32x2 FMA (Blackwell FFMA2; PTX-only, ptxas won't auto-fuse) ----
__device__ __forceinline__ void ffma2(float2 &d, const float2 &a, const float2 &b) {
    unsigned long long &dd = reinterpret_cast<unsigned long long &>(d);
    const unsigned long long &aa = reinterpret_cast<const unsigned long long &>(a);
    const unsigned long long &bb = reinterpret_cast<const unsigned long long &>(b);
    asm("fma.rn.f32x2 %0, %1, %2, %0;" : "+l"(dd) : "l"(aa), "l"(bb));
}

// ============================================================
// SGEMM v3: C[M,N] = A[M,K] @ B[K,N], tile 128x64, BK=16,
// DOUBLE-BUFFERED smem, z-batched over 3 independent (A,B,C) triples.
// 256 threads; per-thread 8x4 outputs as 4 m-pairs x 4 cols (FFMA2).
// All launched shapes divide tiles exactly; K % 16 == 0.
// ============================================================
__global__ __launch_bounds__(256) void sgemm3_kernel(
    const float* __restrict__ A0, const float* __restrict__ A1, const float* __restrict__ A2,
    const float* __restrict__ B0, const float* __restrict__ B1, const float* __restrict__ B2,
    float* __restrict__ C0, float* __restrict__ C1, float* __restrict__ C2,
    int K, int lda, int ldb, int ldc)
{
    const int z = blockIdx.z;
    const float* A = (z == 0) ? A0 : (z == 1) ? A1 : A2;
    const float* B = (z == 0) ? B0 : (z == 1) ? B1 : B2;
    float*       C = (z == 0) ? C0 : (z == 1) ? C1 : C2;

    __shared__ __align__(16) float As[2][16][130];  // [buf][k][m]
    __shared__ __align__(16) float Bs[2][16][68];   // [buf][k][n]
    const int tid = threadIdx.x;
    const int tx = tid & 15, ty = tid >> 4;
    const int m0 = blockIdx.y * 128, n0 = blockIdx.x * 64;

    const int arow0 = tid >> 2,        akq = tid & 3;        // A slot 1
    const int arow1 = (tid + 256) >> 2;                      // A slot 2 (same kq)
    const int bkk = tid >> 4, bnq = tid & 15;                // B slot

    float2 acc[4][4];
#pragma unroll
    for (int i = 0; i < 4; i++)
#pragma unroll
        for (int j = 0; j < 4; j++) acc[i][j] = make_float2(0.f, 0.f);

    // ---- prologue: load tile 0 into buf 0 ----
    {
        float4 a0 = *(const float4*)&A[(size_t)(m0 + arow0) * lda + akq * 4];
        float4 a1 = *(const float4*)&A[(size_t)(m0 + arow1) * lda + akq * 4];
        float4 b  = *(const float4*)&B[(size_t)bkk * ldb + n0 + bnq * 4];
        As[0][akq * 4 + 0][arow0] = a0.x; As[0][akq * 4 + 1][arow0] = a0.y;
        As[0][akq * 4 + 2][arow0] = a0.z; As[0][akq * 4 + 3][arow0] = a0.w;
        As[0][akq * 4 + 0][arow1] = a1.x; As[0][akq * 4 + 1][arow1] = a1.y;
        As[0][akq * 4 + 2][arow1] = a1.z; As[0][akq * 4 + 3][arow1] = a1.w;
        *(float4*)&Bs[0][bkk][bnq * 4] = b;
    }
    __syncthreads();

    const int nIter = K / 16;
    for (int it = 0; it < nIter; it++) {
        const int cur = it & 1, nxt = cur ^ 1;
        float4 a0, a1, b;
        if (it + 1 < nIter) {
            int k0 = (it + 1) * 16;
            a0 = *(const float4*)&A[(size_t)(m0 + arow0) * lda + k0 + akq * 4];
            a1 = *(const float4*)&A[(size_t)(m0 + arow1) * lda + k0 + akq * 4];
            b  = *(const float4*)&B[(size_t)(k0 + bkk) * ldb + n0 + bnq * 4];
        }
#pragma unroll
        for (int kk = 0; kk < 16; kk++) {
            float2 a[4];
#pragma unroll
            for (int i = 0; i < 4; i++) a[i] = *(float2*)&As[cur][kk][ty * 8 + 2 * i];
            float2 bA = *(float2*)&Bs[cur][kk][tx * 4];
            float2 bB = *(float2*)&Bs[cur][kk][tx * 4 + 2];
            float2 bj[4] = {{bA.x, bA.x}, {bA.y, bA.y}, {bB.x, bB.x}, {bB.y, bB.y}};
#pragma unroll
            for (int j = 0; j < 4; j++)
#pragma unroll
                for (int i = 0; i < 4; i++) ffma2(acc[i][j], a[i], bj[j]);
        }
        if (it + 1 < nIter) {
            As[nxt][akq * 4 + 0][arow0] = a0.x; As[nxt][akq * 4 + 1][arow0] = a0.y;
            As[nxt][akq * 4 + 2][arow0] = a0.z; As[nxt][akq * 4 + 3][arow0] = a0.w;
            As[nxt][akq * 4 + 0][arow1] = a1.x; As[nxt][akq * 4 + 1][arow1] = a1.y;
            As[nxt][akq * 4 + 2][arow1] = a1.z; As[nxt][akq * 4 + 3][arow1] = a1.w;
            *(float4*)&Bs[nxt][bkk][bnq * 4] = b;
        }
        __syncthreads();
    }
#pragma unroll
    for (int i = 0; i < 4; i++) {
        int m = m0 + ty * 8 + 2 * i;
        float4 lo = {acc[i][0].x, acc[i][1].x, acc[i][2].x, acc[i][3].x};
        float4 hi = {acc[i][0].y, acc[i][1].y, acc[i][2].y, acc[i][3].y};
        *(float4*)&C[(size_t)m * ldc + n0 + tx * 4] = lo;
        *(float4*)&C[(size_t)(m + 1) * ldc + n0 + tx * 4] = hi;
    }
}

// ============================================================
// SGEMM narrow: N=32 (vp2 projection). tile 128x32, BK=16.
// ============================================================
__global__ __launch_bounds__(256) void sgemm_n32_kernel(
    const float* __restrict__ A, const float* __restrict__ B, float* __restrict__ C,
    int K, int lda)
{
    __shared__ __align__(16) float As[2][16][130];
    __shared__ __align__(16) float Bs[2][16][36];
    const int tid = threadIdx.x;
    const int tx = tid & 7, ty = tid >> 3;
    const int m0 = blockIdx.y * 128;

    const int arow0 = tid >> 2, akq = tid & 3;
    const int arow1 = (tid + 256) >> 2;

    float2 acc[2][4];
#pragma unroll
    for (int i = 0; i < 2; i++)
#pragma unroll
        for (int j = 0; j < 4; j++) acc[i][j] = make_float2(0.f, 0.f);

    {
        float4 a0 = *(const float4*)&A[(size_t)(m0 + arow0) * lda + akq * 4];
        float4 a1 = *(const float4*)&A[(size_t)(m0 + arow1) * lda + akq * 4];
        As[0][akq * 4 + 0][arow0] = a0.x; As[0][akq * 4 + 1][arow0] = a0.y;
        As[0][akq * 4 + 2][arow0] = a0.z; As[0][akq * 4 + 3][arow0] = a0.w;
        As[0][akq * 4 + 0][arow1] = a1.x; As[0][akq * 4 + 1][arow1] = a1.y;
        As[0][akq * 4 + 2][arow1] = a1.z; As[0][akq * 4 + 3][arow1] = a1.w;
        if (tid < 128) {
            int kk = tid >> 3, nq = tid & 7;
            *(float4*)&Bs[0][kk][nq * 4] = *(const float4*)&B[(size_t)kk * DKV + nq * 4];
        }
    }
    __syncthreads();

    const int nIter = K / 16;
    for (int it = 0; it < nIter; it++) {
        const int cur = it & 1, nxt = cur ^ 1;
        float4 a0, a1, b;
        if (it + 1 < nIter) {
            int k0 = (it + 1) * 16;
            a0 = *(const float4*)&A[(size_t)(m0 + arow0) * lda + k0 + akq * 4];
            a1 = *(const float4*)&A[(size_t)(m0 + arow1) * lda + k0 + akq * 4];
            if (tid < 128) {
                int kk = tid >> 3, nq = tid & 7;
                b = *(const float4*)&B[(size_t)(k0 + kk) * DKV + nq * 4];
            }
        }
#pragma unroll
        for (int kk = 0; kk < 16; kk++) {
            float2 a0s = *(float2*)&As[cur][kk][ty * 4];
            float2 a1s = *(float2*)&As[cur][kk][ty * 4 + 2];
            float2 bA = *(float2*)&Bs[cur][kk][tx * 4];
            float2 bB = *(float2*)&Bs[cur][kk][tx * 4 + 2];
            float2 bj[4] = {{bA.x, bA.x}, {bA.y, bA.y}, {bB.x, bB.x}, {bB.y, bB.y}};
#pragma unroll
            for (int j = 0; j < 4; j++) { ffma2(acc[0][j], a0s, bj[j]); ffma2(acc[1][j], a1s, bj[j]); }
        }
        if (it + 1 < nIter) {
            As[nxt][akq * 4 + 0][arow0] = a0.x; As[nxt][akq * 4 + 1][arow0] = a0.y;
            As[nxt][akq * 4 + 2][arow0] = a0.z; As[nxt][akq * 4 + 3][arow0] = a0.w;
            As[nxt][akq * 4 + 0][arow1] = a1.x; As[nxt][akq * 4 + 1][arow1] = a1.y;
            As[nxt][akq * 4 + 2][arow1] = a1.z; As[nxt][akq * 4 + 3][arow1] = a1.w;
            if (tid < 128) {
                int kk = tid >> 3, nq = tid & 7;
                *(float4*)&Bs[nxt][kk][nq * 4] = b;
            }
        }
        __syncthreads();
    }
#pragma unroll
    for (int i = 0; i < 2; i++) {
        int m = m0 + ty * 4 + 2 * i;
        float4 lo = {acc[i][0].x, acc[i][1].x, acc[i][2].x, acc[i][3].x};
        float4 hi = {acc[i][0].y, acc[i][1].y, acc[i][2].y, acc[i][3].y};
        *(float4*)&C[(size_t)m * DKV + tx * 4] = lo;
        *(float4*)&C[(size_t)(m + 1) * DKV + tx * 4] = hi;
    }
}

// ============================================================
// Fused attention v3: Q in registers, DOUBLE-BUFFERED K/V tiles,
// FFMA2 scores/AV, float4 softmax + attn write.
// grid (S/16, H, B), 256 threads.
// ============================================================
__global__ __launch_bounds__(256) void attn3_kernel(
    const float* __restrict__ Q, const float* __restrict__ K, const float* __restrict__ V,
    const int* __restrict__ mask, float* __restrict__ attn, float* __restrict__ ctx)
{
    const int q0 = blockIdx.x * 16;
    const int h = blockIdx.y;
    const int b = blockIdx.z;
    const int tid = threadIdx.x;
    const int lane = tid & 31, warp = tid >> 5;

    __shared__ __align__(16) float  Sb[16][528];       // bank-shifted rows
    __shared__ __align__(16) float2 KV2[2][64][17];    // double-buffered K/V chunk

    // ---- stage Q scaled (buf 0), pull own row into registers ----
    {
        int sq = tid >> 4, dp = tid & 15;
        float2 v = *(const float2*)&Q[((size_t)(b * SS + q0 + sq)) * DM + h * DKV + dp * 2];
        v.x *= 0.17677669529663687f; v.y *= 0.17677669529663687f;
        KV2[0][sq][dp] = v;
    }
    __syncthreads();
    const int qq = (warp << 1) | (lane >> 4);
    float2 qr[16];
#pragma unroll
    for (int dp = 0; dp < 16; dp++) qr[dp] = KV2[0][qq][dp];
    __syncthreads();

    const long long mrow0 = (((long long)(b * HH + h)) * SS + q0) * SS;
    const int lrow = tid >> 4, ldp = tid & 15;  // loader mapping (4 rows per pass)

    // ---- scores + mask (double-buffered K) ----
    // prologue: K tile 0 -> buf 0
#pragma unroll
    for (int t = 0; t < 4; t++) {
        int kk = lrow + t * 16;
        KV2[0][kk][ldp] = *(const float2*)&K[((size_t)(b * SS + kk)) * DM + h * DKV + ldp * 2];
    }
    __syncthreads();
    const int kb = lane & 15;
    for (int it = 0; it < 8; it++) {
        const int cur = it & 1, nxt = cur ^ 1;
        const int k0 = it * 64;
        float2 pre[4];
        if (it < 7) {
#pragma unroll
            for (int t = 0; t < 4; t++) {
                int kk = lrow + t * 16;
                pre[t] = *(const float2*)&K[((size_t)(b * SS + k0 + 64 + kk)) * DM + h * DKV + ldp * 2];
            }
        }
        // mask prefetch for this thread's 4 outputs
        int mk[4];
#pragma unroll
        for (int jj = 0; jj < 4; jj++)
            mk[jj] = mask[mrow0 + (long long)qq * SS + k0 + kb + jj * 16];
#pragma unroll
        for (int jj = 0; jj < 4; jj++) {
            int kk = kb + jj * 16;
            float2 acc = make_float2(0.f, 0.f);
#pragma unroll
            for (int dp = 0; dp < 16; dp++) ffma2(acc, qr[dp], KV2[cur][kk][dp]);
            Sb[qq][k0 + kk] = mk[jj] ? -1e9f : (acc.x + acc.y);
        }
        if (it < 7) {
#pragma unroll
            for (int t = 0; t < 4; t++) KV2[nxt][lrow + t * 16][ldp] = pre[t];
        }
        __syncthreads();
    }

    // ---- softmax (warp-local rows 2w, 2w+1) + write attn ----
#pragma unroll
    for (int rr = 0; rr < 2; rr++) {
        int q = (warp << 1) | rr;
        float mx = -1e30f;
#pragma unroll
        for (int t = 0; t < 4; t++) {
            float4 v = *(float4*)&Sb[q][(lane + t * 32) * 4];
            mx = fmaxf(mx, fmaxf(fmaxf(v.x, v.y), fmaxf(v.z, v.w)));
        }
#pragma unroll
        for (int o = 16; o; o >>= 1) mx = fmaxf(mx, __shfl_xor_sync(0xffffffffu, mx, o));
        float sum = 0.f;
#pragma unroll
        for (int t = 0; t < 4; t++) {
            float4 v = *(float4*)&Sb[q][(lane + t * 32) * 4];
            v.x = __expf(v.x - mx); v.y = __expf(v.y - mx);
            v.z = __expf(v.z - mx); v.w = __expf(v.w - mx);
            *(float4*)&Sb[q][(lane + t * 32) * 4] = v;
            sum += v.x + v.y + v.z + v.w;
        }
#pragma unroll
        for (int o = 16; o; o >>= 1) sum += __shfl_xor_sync(0xffffffffu, sum, o);
        float inv = 1.f / sum;
        long long base = mrow0 + (long long)q * SS;
#pragma unroll
        for (int t = 0; t < 4; t++) {
            float4 v = *(float4*)&Sb[q][(lane + t * 32) * 4];
            v.x *= inv; v.y *= inv; v.z *= inv; v.w *= inv;
            *(float4*)&Sb[q][(lane + t * 32) * 4] = v;
            *(float4*)&attn[base + (lane + t * 32) * 4] = v;
        }
    }
    __syncthreads();

    // ---- attn @ V (double-buffered V) ----
    {
        const int cq = tid >> 4, dp = tid & 15;
        float2 acc = make_float2(0.f, 0.f);
        // prologue: V tile 0 -> buf 0
#pragma unroll
        for (int t = 0; t < 4; t++) {
            int kk = lrow + t * 16;
            KV2[0][kk][ldp] = *(const float2*)&V[((size_t)(b * SS + kk)) * DM + h * DKV + ldp * 2];
        }
        __syncthreads();
        for (int it = 0; it < 8; it++) {
            const int cur = it & 1, nxt = cur ^ 1;
            const int k0 = it * 64;
            float2 pre[4];
            if (it < 7) {
#pragma unroll
                for (int t = 0; t < 4; t++) {
                    int kk = lrow + t * 16;
                    pre[t] = *(const float2*)&V[((size_t)(b * SS + k0 + 64 + kk)) * DM + h * DKV + ldp * 2];
                }
            }
#pragma unroll
            for (int kp = 0; kp < 32; kp++) {
                float2 ap = *(const float2*)&Sb[cq][k0 + 2 * kp];
                float2 a0 = {ap.x, ap.x}, a1 = {ap.y, ap.y};
                ffma2(acc, a0, KV2[cur][2 * kp][dp]);
                ffma2(acc, a1, KV2[cur][2 * kp + 1][dp]);
            }
            if (it < 7) {
#pragma unroll
                for (int t = 0; t < 4; t++) KV2[nxt][lrow + t * 16][ldp] = pre[t];
            }
            __syncthreads();
        }
        *(float2*)&ctx[((size_t)(b * SS + q0 + cq)) * CTXW + h * DKV + dp * 2] = acc;
    }
}

// ============================================================
// context2 = matrix @ vp2 -> ctx cols [256, 288). tile 32 rows.
// ============================================================
__global__ __launch_bounds__(256) void ctx2_kernel(
    const float* __restrict__ matrix, const float* __restrict__ vp2, float* __restrict__ ctx)
{
    __shared__ __align__(16) float  Ms[32][68];
    __shared__ __align__(16) float2 Vs[64][17];
    const int b = blockIdx.y, i0 = blockIdx.x * 32;
    const int tid = threadIdx.x;
    const int r = tid >> 3, cq = tid & 7;

    float2 acc0 = make_float2(0.f, 0.f), acc1 = make_float2(0.f, 0.f);
    for (int k0 = 0; k0 < SS; k0 += 64) {
#pragma unroll
        for (int t = 0; t < 2; t++) {
            int idx = tid + t * 256;
            int row = idx >> 4, c4 = idx & 15;
            *(float4*)&Ms[row][c4 * 4] =
                *(const float4*)&matrix[((size_t)(b * SS + i0 + row)) * SS + k0 + c4 * 4];
        }
#pragma unroll
        for (int t = 0; t < 4; t++) {
            int idx = tid + t * 256, kk = idx >> 4, dp = idx & 15;
            Vs[kk][dp] = *(const float2*)&vp2[((size_t)(b * SS + k0 + kk)) * DKV + dp * 2];
        }
        __syncthreads();
#pragma unroll
        for (int kk = 0; kk < 64; kk++) {
            float a = Ms[r][kk];
            float2 a2 = {a, a};
            ffma2(acc0, a2, Vs[kk][cq * 2]);
            ffma2(acc1, a2, Vs[kk][cq * 2 + 1]);
        }
        __syncthreads();
    }
    float4 o4 = {acc0.x, acc0.y, acc1.x, acc1.y};
    *(float4*)&ctx[((size_t)(b * SS + i0 + r)) * CTXW + HH * DKV + cq * 4] = o4;
}

// ============================================================
// Gate: per (b,i,j): v = [matrix[b,j,i], attn[b,:,j,i]] (9 ch),
// LN -> relu(9->6) -> sigmoid(6->1); matrix_out = matrix * g
// ============================================================
__global__ __launch_bounds__(256) void gate_kernel(
    const float* __restrict__ attn, const float* __restrict__ matrix, float* __restrict__ mout,
    const float* __restrict__ fu_ln_g, const float* __restrict__ fu_ln_b,
    const float* __restrict__ fu_w1, const float* __restrict__ fu_b1,
    const float* __restrict__ fu_w2, const float* __restrict__ fu_b2)
{
    __shared__ float pl[9][32][33];
    __shared__ float pg[9], pb[9], w1[9][6], b1[6], w2[6], b2s;

    int b = blockIdx.z;
    int i0 = blockIdx.y * 32, j0 = blockIdx.x * 32;
    int tid = threadIdx.x;

    if (tid < 9) { pg[tid] = fu_ln_g[tid]; pb[tid] = fu_ln_b[tid]; }
    if (tid >= 32 && tid < 86) { int t = tid - 32; w1[t / 6][t % 6] = fu_w1[t]; }
    if (tid >= 96 && tid < 102) b1[tid - 96] = fu_b1[tid - 96];
    if (tid >= 128 && tid < 134) w2[tid - 128] = fu_w2[tid - 128];
    if (tid == 160) b2s = fu_b2[0];

    for (int c = 0; c < 9; c++) {
        const float* src = (c == 0) ? (matrix + (long long)b * SS * SS)
                                    : (attn + ((long long)(b * HH + c - 1)) * SS * SS);
        for (int i = tid; i < 1024; i += 256) {
            int jj = i >> 5, ii = i & 31;
            pl[c][jj][ii] = src[(long long)(j0 + jj) * SS + i0 + ii];
        }
    }
    __syncthreads();

#pragma unroll
    for (int r = 0; r < 4; r++) {
        int idx = tid + r * 256;
        int ii = idx >> 5, jj = idx & 31;
        float v[9];
        float m = 0.f;
#pragma unroll
        for (int c = 0; c < 9; c++) { v[c] = pl[c][jj][ii]; m += v[c]; }
        m *= (1.f / 9.f);
        float var = 0.f;
#pragma unroll
        for (int c = 0; c < 9; c++) { float dd = v[c] - m; var += dd * dd; }
        var *= (1.f / 9.f);
        float rinv = rsqrtf(var + EPS);
        float y[9];
#pragma unroll
        for (int c = 0; c < 9; c++) y[c] = pg[c] * (v[c] - m) * rinv + pb[c];
        float z = b2s;
#pragma unroll
        for (int j = 0; j < 6; j++) {
            float t = b1[j];
#pragma unroll
            for (int c = 0; c < 9; c++) t += y[c] * w1[c][j];
            t = fmaxf(t, 0.f);
            z += t * w2[j];
        }
        float g = 1.f / (1.f + __expf(-z));
        long long o = ((long long)b * SS + i0 + ii) * SS + j0 + jj;
        mout[o] = matrix[o] * g;
    }
}

// ============================================================
// Final layernorm over 256 channels: one block per row
// ============================================================
__global__ __launch_bounds__(256) void ln_kernel(
    const float* __restrict__ x, const float* __restrict__ g,
    const float* __restrict__ bt, float* __restrict__ out)
{
    int row = blockIdx.x, tid = threadIdx.x;
    float v = x[(long long)row * DM + tid];

    __shared__ float red[8];
    float s = v;
#pragma unroll
    for (int o = 16; o; o >>= 1) s += __shfl_xor_sync(0xffffffffu, s, o);
    if ((tid & 31) == 0) red[tid >> 5] = s;
    __syncthreads();
    float tot = 0.f;
#pragma unroll
    for (int i = 0; i < 8; i++) tot += red[i];
    float m = tot * (1.f / DM);
    __syncthreads();

    float d = v - m;
    float s2 = d * d;
#pragma unroll
    for (int o = 16; o; o >>= 1) s2 += __shfl_xor_sync(0xffffffffu, s2, o);
    if ((tid & 31) == 0) red[tid >> 5] = s2;
    __syncthreads();
    float vtot = 0.f;
#pragma unroll
    for (int i = 0; i < 8; i++) vtot += red[i];
    float var = vtot * (1.f / DM);

    out[(long long)row * DM + tid] = g[tid] * d * rsqrtf(var + EPS) + bt[tid];
}

// ============================================================
extern "C" void kernel_launch(void* const* d_in, const int* in_sizes, int n_in,
                              void* d_out, int out_size)
{
    const float* inQ    = (const float*)d_in[0];
    const float* inK    = (const float*)d_in[1];
    const float* inV    = (const float*)d_in[2];
    const int*   mask   = (const int*)  d_in[3];
    const float* matrix = (const float*)d_in[4];
    const float* W_Q    = (const float*)d_in[5];
    const float* W_K    = (const float*)d_in[6];
    const float* W_V    = (const float*)d_in[7];
    const float* W_V2   = (const float*)d_in[8];
    const float* W_fc   = (const float*)d_in[9];
    const float* ln_g   = (const float*)d_in[10];
    const float* ln_b   = (const float*)d_in[11];
    const float* fu_ln_g= (const float*)d_in[12];
    const float* fu_ln_b= (const float*)d_in[13];
    const float* fu_w1  = (const float*)d_in[14];
    const float* fu_b1  = (const float*)d_in[15];
    const float* fu_w2  = (const float*)d_in[16];
    const float* fu_b2  = (const float*)d_in[17];

    float* out  = (float*)d_out;                            // [B,S,DM]
    float* mout = (float*)d_out + (long long)BB * SS * DM;  // [B,S,S]

    float *pQ, *pK, *pV, *pattn, *pvp2, *pctx, *pfc;
    cudaGetSymbolAddress((void**)&pQ, g_Q);
    cudaGetSymbolAddress((void**)&pK, g_K);
    cudaGetSymbolAddress((void**)&pV, g_V);
    cudaGetSymbolAddress((void**)&pattn, g_attn);
    cudaGetSymbolAddress((void**)&pvp2, g_vp2);
    cudaGetSymbolAddress((void**)&pctx, g_ctx);
    cudaGetSymbolAddress((void**)&pfc, g_fc);

    // QKV projections in ONE launch (z-batched): [8192,256] @ [256,256]
    sgemm3_kernel<<<dim3(4, 64, 3), 256>>>(inQ, inK, inV, W_Q, W_K, W_V,
                                           pQ, pK, pV, DM, DM, DM, DM);
    // vp2 = input_V @ W_V2 : [8192,256] @ [256,32]
    sgemm_n32_kernel<<<dim3(1, 64), 256>>>(inV, W_V2, pvp2, DM, DM);

    // fused attention (writes attn + ctx cols 0..255)
    attn3_kernel<<<dim3(SS / 16, HH, BB), 256>>>(pQ, pK, pV, mask, pattn, pctx);

    // context2 = matrix @ vp2 -> ctx cols 256..287
    ctx2_kernel<<<dim3(16, BB), 256>>>(matrix, pvp2, pctx);

    // fc: [8192,288] @ [288,256]
    sgemm3_kernel<<<dim3(4, 64, 1), 256>>>(pctx, pctx, pctx, W_fc, W_fc, W_fc,
                                           pfc, pfc, pfc, CTXW, CTXW, DM, DM);

    // final layernorm -> output
    ln_kernel<<<BB * SS, 256>>>(pfc, ln_g, ln_b, out);

    // gate -> matrix_out (independent of fc/ln; last so tail overlaps nothing it blocks)
    gate_kernel<<<dim3(SS / 32, SS / 32, BB), 256>>>(pattn, matrix, mout,
                                                     fu_ln_g, fu_ln_b, fu_w1, fu_b1, fu_w2, fu_b2);
}

// round 7
// speedup vs baseline: 1.8265x; 1.8265x over previous
#include <cuda_runtime.h>
#include <math.h>

// Problem constants
#define BB 16
#define SS 512
#define DM 256
#define HH 8
#define DKV 32
#define CTXW 288   // DV*(H+1)
#define EPS 1e-5f

// -------- scratch (device globals; no allocation allowed) --------
__device__ float g_Q[BB * SS * DM];
__device__ float g_K[BB * SS * DM];
__device__ float g_V[BB * SS * DM];
__device__ float g_attn[(long)BB * HH * SS * SS];   // 134 MB
__device__ float g_vp2[BB * SS * DKV];
__device__ float g_ctx[BB * SS * CTXW];
__device__ float g_fc[BB * SS * DM];

// ---- packed f32x2 FMA (Blackwell FFMA2; PTX-only, ptxas won't auto-fuse) ----
__device__ __forceinline__ void ffma2(float2 &d, const float2 &a, const float2 &b) {
    unsigned long long &dd = reinterpret_cast<unsigned long long &>(d);
    const unsigned long long &aa = reinterpret_cast<const unsigned long long &>(a);
    const unsigned long long &bb = reinterpret_cast<const unsigned long long &>(b);
    asm("fma.rn.f32x2 %0, %1, %2, %0;" : "+l"(dd) : "l"(aa), "l"(bb));
}

// ============================================================
// SGEMM v2 (R4 single-buffered inner loop), z-dispatched over up to
// 3 independent (A,B,C) triples. tile 128x64, BK=16, 256 threads,
// per-thread 8x4 outputs as 4 m-pairs x 4 cols (FFMA2).
// ============================================================
__global__ __launch_bounds__(256) void sgemm2_kernel(
    const float* __restrict__ A0, const float* __restrict__ A1, const float* __restrict__ A2,
    const float* __restrict__ B0, const float* __restrict__ B1, const float* __restrict__ B2,
    float* __restrict__ C0, float* __restrict__ C1, float* __restrict__ C2,
    int K, int lda, int ldb, int ldc)
{
    const int z = blockIdx.z;
    const float* A = (z == 0) ? A0 : (z == 1) ? A1 : A2;
    const float* B = (z == 0) ? B0 : (z == 1) ? B1 : B2;
    float*       C = (z == 0) ? C0 : (z == 1) ? C1 : C2;

    __shared__ __align__(16) float As[16][130];  // [k][m], m contiguous
    __shared__ __align__(16) float Bs[16][68];   // [k][n]
    const int tid = threadIdx.x;
    const int tx = tid & 15, ty = tid >> 4;
    const int m0 = blockIdx.y * 128, n0 = blockIdx.x * 64;

    float2 acc[4][4];
#pragma unroll
    for (int i = 0; i < 4; i++)
#pragma unroll
        for (int j = 0; j < 4; j++) acc[i][j] = make_float2(0.f, 0.f);

    for (int k0 = 0; k0 < K; k0 += 16) {
#pragma unroll
        for (int t = 0; t < 2; t++) {
            int idx = tid + t * 256;              // 0..511 float4 slots (128 rows x 4)
            int row = idx >> 2, kq = idx & 3;
            float4 v = *(const float4*)&A[(size_t)(m0 + row) * lda + k0 + kq * 4];
            As[kq * 4 + 0][row] = v.x; As[kq * 4 + 1][row] = v.y;
            As[kq * 4 + 2][row] = v.z; As[kq * 4 + 3][row] = v.w;
        }
        {
            int kk = tid >> 4, nq = tid & 15;
            *(float4*)&Bs[kk][nq * 4] =
                *(const float4*)&B[(size_t)(k0 + kk) * ldb + n0 + nq * 4];
        }
        __syncthreads();
#pragma unroll
        for (int kk = 0; kk < 16; kk++) {
            float2 a[4];
#pragma unroll
            for (int i = 0; i < 4; i++) a[i] = *(float2*)&As[kk][ty * 8 + 2 * i];
            float2 bA = *(float2*)&Bs[kk][tx * 4];
            float2 bB = *(float2*)&Bs[kk][tx * 4 + 2];
            float2 bj[4] = {{bA.x, bA.x}, {bA.y, bA.y}, {bB.x, bB.x}, {bB.y, bB.y}};
#pragma unroll
            for (int j = 0; j < 4; j++)
#pragma unroll
                for (int i = 0; i < 4; i++) ffma2(acc[i][j], a[i], bj[j]);
        }
        __syncthreads();
    }
#pragma unroll
    for (int i = 0; i < 4; i++) {
        int m = m0 + ty * 8 + 2 * i;
        float4 lo = {acc[i][0].x, acc[i][1].x, acc[i][2].x, acc[i][3].x};
        float4 hi = {acc[i][0].y, acc[i][1].y, acc[i][2].y, acc[i][3].y};
        *(float4*)&C[(size_t)m * ldc + n0 + tx * 4] = lo;
        *(float4*)&C[(size_t)(m + 1) * ldc + n0 + tx * 4] = hi;
    }
}

// ============================================================
// SGEMM narrow: N=32 (vp2 projection). tile 128x32, BK=16. (R4 version)
// ============================================================
__global__ __launch_bounds__(256) void sgemm_n32_kernel(
    const float* __restrict__ A, const float* __restrict__ B, float* __restrict__ C,
    int K, int lda)
{
    __shared__ __align__(16) float As[16][130];
    __shared__ __align__(16) float Bs[16][36];
    const int tid = threadIdx.x;
    const int tx = tid & 7, ty = tid >> 3;   // 8 col-groups x 32 row-groups
    const int m0 = blockIdx.y * 128;

    float2 acc[2][4];
#pragma unroll
    for (int i = 0; i < 2; i++)
#pragma unroll
        for (int j = 0; j < 4; j++) acc[i][j] = make_float2(0.f, 0.f);

    for (int k0 = 0; k0 < K; k0 += 16) {
#pragma unroll
        for (int t = 0; t < 2; t++) {
            int idx = tid + t * 256;
            int row = idx >> 2, kq = idx & 3;
            float4 v = *(const float4*)&A[(size_t)(m0 + row) * lda + k0 + kq * 4];
            As[kq * 4 + 0][row] = v.x; As[kq * 4 + 1][row] = v.y;
            As[kq * 4 + 2][row] = v.z; As[kq * 4 + 3][row] = v.w;
        }
        if (tid < 128) {
            int kk = tid >> 3, nq = tid & 7;
            *(float4*)&Bs[kk][nq * 4] =
                *(const float4*)&B[(size_t)(k0 + kk) * DKV + nq * 4];
        }
        __syncthreads();
#pragma unroll
        for (int kk = 0; kk < 16; kk++) {
            float2 a0 = *(float2*)&As[kk][ty * 4];
            float2 a1 = *(float2*)&As[kk][ty * 4 + 2];
            float2 bA = *(float2*)&Bs[kk][tx * 4];
            float2 bB = *(float2*)&Bs[kk][tx * 4 + 2];
            float2 bj[4] = {{bA.x, bA.x}, {bA.y, bA.y}, {bB.x, bB.x}, {bB.y, bB.y}};
#pragma unroll
            for (int j = 0; j < 4; j++) { ffma2(acc[0][j], a0, bj[j]); ffma2(acc[1][j], a1, bj[j]); }
        }
        __syncthreads();
    }
#pragma unroll
    for (int i = 0; i < 2; i++) {
        int m = m0 + ty * 4 + 2 * i;
        float4 lo = {acc[i][0].x, acc[i][1].x, acc[i][2].x, acc[i][3].x};
        float4 hi = {acc[i][0].y, acc[i][1].y, acc[i][2].y, acc[i][3].y};
        *(float4*)&C[(size_t)m * DKV + tx * 4] = lo;
        *(float4*)&C[(size_t)(m + 1) * DKV + tx * 4] = hi;
    }
}

// ============================================================
// Fused attention v2 (R4): Q in registers, single-buffered K/V tiles,
// FFMA2 scores / AV, float4 softmax + attn write. grid (S/16, H, B).
// ============================================================
__global__ __launch_bounds__(256) void attn2_kernel(
    const float* __restrict__ Q, const float* __restrict__ K, const float* __restrict__ V,
    const int* __restrict__ mask, float* __restrict__ attn, float* __restrict__ ctx)
{
    const int q0 = blockIdx.x * 16;
    const int h = blockIdx.y;
    const int b = blockIdx.z;
    const int tid = threadIdx.x;
    const int lane = tid & 31, warp = tid >> 5;

    __shared__ __align__(16) float  Sb[16][528];     // stride 528: bank-shifted rows
    __shared__ __align__(16) float2 KV2[64][17];     // K/V chunk (also Q staging)

    // ---- stage Q scaled, then pull own row into registers ----
    {
        int sq = tid >> 4, dp = tid & 15;
        float2 v = *(const float2*)&Q[((size_t)(b * SS + q0 + sq)) * DM + h * DKV + dp * 2];
        v.x *= 0.17677669529663687f; v.y *= 0.17677669529663687f;
        KV2[sq][dp] = v;
    }
    __syncthreads();
    const int qq = (warp << 1) | (lane >> 4);
    float2 qr[16];
#pragma unroll
    for (int dp = 0; dp < 16; dp++) qr[dp] = KV2[qq][dp];
    __syncthreads();

    const long long mrow0 = (((long long)(b * HH + h)) * SS + q0) * SS;

    // ---- scores + mask ----
    for (int k0 = 0; k0 < SS; k0 += 64) {
#pragma unroll
        for (int t = 0; t < 4; t++) {
            int idx = tid + t * 256, kk = idx >> 4, dp = idx & 15;
            KV2[kk][dp] = *(const float2*)&K[((size_t)(b * SS + k0 + kk)) * DM + h * DKV + dp * 2];
        }
        __syncthreads();
        int kb = lane & 15;
#pragma unroll
        for (int jj = 0; jj < 4; jj++) {
            int kk = kb + jj * 16;
            float2 acc = make_float2(0.f, 0.f);
#pragma unroll
            for (int dp = 0; dp < 16; dp++) ffma2(acc, qr[dp], KV2[kk][dp]);
            float s = acc.x + acc.y;
            int mk = mask[mrow0 + (long long)qq * SS + k0 + kk];
            Sb[qq][k0 + kk] = mk ? -1e9f : s;
        }
        __syncthreads();
    }

    // ---- softmax (warp-local rows 2w, 2w+1) + write attn ----
#pragma unroll
    for (int rr = 0; rr < 2; rr++) {
        int q = (warp << 1) | rr;
        float mx = -1e30f;
#pragma unroll
        for (int t = 0; t < 4; t++) {
            float4 v = *(float4*)&Sb[q][(lane + t * 32) * 4];
            mx = fmaxf(mx, fmaxf(fmaxf(v.x, v.y), fmaxf(v.z, v.w)));
        }
#pragma unroll
        for (int o = 16; o; o >>= 1) mx = fmaxf(mx, __shfl_xor_sync(0xffffffffu, mx, o));
        float sum = 0.f;
#pragma unroll
        for (int t = 0; t < 4; t++) {
            float4 v = *(float4*)&Sb[q][(lane + t * 32) * 4];
            v.x = __expf(v.x - mx); v.y = __expf(v.y - mx);
            v.z = __expf(v.z - mx); v.w = __expf(v.w - mx);
            *(float4*)&Sb[q][(lane + t * 32) * 4] = v;
            sum += v.x + v.y + v.z + v.w;
        }
#pragma unroll
        for (int o = 16; o; o >>= 1) sum += __shfl_xor_sync(0xffffffffu, sum, o);
        float inv = 1.f / sum;
        long long base = mrow0 + (long long)q * SS;
#pragma unroll
        for (int t = 0; t < 4; t++) {
            float4 v = *(float4*)&Sb[q][(lane + t * 32) * 4];
            v.x *= inv; v.y *= inv; v.z *= inv; v.w *= inv;
            *(float4*)&Sb[q][(lane + t * 32) * 4] = v;
            *(float4*)&attn[base + (lane + t * 32) * 4] = v;
        }
    }

    // ---- attn @ V ----
    {
        const int cq = tid >> 4, dp = tid & 15;
        float2 acc = make_float2(0.f, 0.f);
        for (int k0 = 0; k0 < SS; k0 += 64) {
#pragma unroll
            for (int t = 0; t < 4; t++) {
                int idx = tid + t * 256, kk = idx >> 4, dq = idx & 15;
                KV2[kk][dq] = *(const float2*)&V[((size_t)(b * SS + k0 + kk)) * DM + h * DKV + dq * 2];
            }
            __syncthreads();
#pragma unroll
            for (int kp = 0; kp < 32; kp++) {
                float2 ap = *(const float2*)&Sb[cq][k0 + 2 * kp];
                float2 a0 = {ap.x, ap.x}, a1 = {ap.y, ap.y};
                ffma2(acc, a0, KV2[2 * kp][dp]);
                ffma2(acc, a1, KV2[2 * kp + 1][dp]);
            }
            __syncthreads();
        }
        *(float2*)&ctx[((size_t)(b * SS + q0 + cq)) * CTXW + h * DKV + dp * 2] = acc;
    }
}

// ============================================================
// context2 = matrix @ vp2 -> ctx cols [256, 288). (R4 version)
// ============================================================
__global__ __launch_bounds__(256) void ctx2_kernel(
    const float* __restrict__ matrix, const float* __restrict__ vp2, float* __restrict__ ctx)
{
    __shared__ __align__(16) float  Ms[32][68];
    __shared__ __align__(16) float2 Vs[64][17];
    const int b = blockIdx.y, i0 = blockIdx.x * 32;
    const int tid = threadIdx.x;
    const int r = tid >> 3, cq = tid & 7;

    float2 acc0 = make_float2(0.f, 0.f), acc1 = make_float2(0.f, 0.f);
    for (int k0 = 0; k0 < SS; k0 += 64) {
#pragma unroll
        for (int t = 0; t < 2; t++) {
            int idx = tid + t * 256;
            int row = idx >> 4, c4 = idx & 15;
            *(float4*)&Ms[row][c4 * 4] =
                *(const float4*)&matrix[((size_t)(b * SS + i0 + row)) * SS + k0 + c4 * 4];
        }
#pragma unroll
        for (int t = 0; t < 4; t++) {
            int idx = tid + t * 256, kk = idx >> 4, dp = idx & 15;
            Vs[kk][dp] = *(const float2*)&vp2[((size_t)(b * SS + k0 + kk)) * DKV + dp * 2];
        }
        __syncthreads();
#pragma unroll
        for (int kk = 0; kk < 64; kk++) {
            float a = Ms[r][kk];
            float2 a2 = {a, a};
            ffma2(acc0, a2, Vs[kk][cq * 2]);
            ffma2(acc1, a2, Vs[kk][cq * 2 + 1]);
        }
        __syncthreads();
    }
    float4 o4 = {acc0.x, acc0.y, acc1.x, acc1.y};
    *(float4*)&ctx[((size_t)(b * SS + i0 + r)) * CTXW + HH * DKV + cq * 4] = o4;
}

// ============================================================
// Gate v2: per (b,i,j): v = [matrix[b,j,i], attn[b,:,j,i]] (9 ch),
// LN -> relu(9->6) -> sigmoid(6->1); matrix_out = matrix * g.
// R6 CHANGE: all 36 global loads issued back-to-back into registers
// (MLP ~36/thread) before any smem store — attack latency-bound loads.
// ============================================================
__global__ __launch_bounds__(256) void gate_kernel(
    const float* __restrict__ attn, const float* __restrict__ matrix, float* __restrict__ mout,
    const float* __restrict__ fu_ln_g, const float* __restrict__ fu_ln_b,
    const float* __restrict__ fu_w1, const float* __restrict__ fu_b1,
    const float* __restrict__ fu_w2, const float* __restrict__ fu_b2)
{
    __shared__ float pl[9][32][33];
    __shared__ float pg[9], pb[9], w1[9][6], b1[6], w2[6], b2s;

    int b = blockIdx.z;
    int i0 = blockIdx.y * 32, j0 = blockIdx.x * 32;
    int tid = threadIdx.x;

    if (tid < 9) { pg[tid] = fu_ln_g[tid]; pb[tid] = fu_ln_b[tid]; }
    if (tid >= 32 && tid < 86) { int t = tid - 32; w1[t / 6][t % 6] = fu_w1[t]; }
    if (tid >= 96 && tid < 102) b1[tid - 96] = fu_b1[tid - 96];
    if (tid >= 128 && tid < 134) w2[tid - 128] = fu_w2[tid - 128];
    if (tid == 160) b2s = fu_b2[0];

    // ---- all 36 loads first (9 planes x 4 positions), then stores ----
    {
        const int jj0 = tid >> 5, ii = tid & 31;   // 4 jj rows per thread: jj0, jj0+8, +16, +24
        const float* srcs[9];
        srcs[0] = matrix + (size_t)b * SS * SS;
#pragma unroll
        for (int c = 1; c < 9; c++)
            srcs[c] = attn + ((size_t)(b * HH + c - 1)) * SS * SS;

        float vals[9][4];
#pragma unroll
        for (int c = 0; c < 9; c++)
#pragma unroll
            for (int t = 0; t < 4; t++)
                vals[c][t] = srcs[c][(size_t)(j0 + jj0 + t * 8) * SS + i0 + ii];

#pragma unroll
        for (int c = 0; c < 9; c++)
#pragma unroll
            for (int t = 0; t < 4; t++)
                pl[c][jj0 + t * 8][ii] = vals[c][t];
    }
    __syncthreads();

#pragma unroll
    for (int r = 0; r < 4; r++) {
        int idx = tid + r * 256;
        int ii = idx >> 5, jj = idx & 31;   // jj fastest -> coalesced writes
        float v[9];
        float m = 0.f;
#pragma unroll
        for (int c = 0; c < 9; c++) { v[c] = pl[c][jj][ii]; m += v[c]; }
        m *= (1.f / 9.f);
        float var = 0.f;
#pragma unroll
        for (int c = 0; c < 9; c++) { float dd = v[c] - m; var += dd * dd; }
        var *= (1.f / 9.f);
        float rinv = rsqrtf(var + EPS);
        float y[9];
#pragma unroll
        for (int c = 0; c < 9; c++) y[c] = pg[c] * (v[c] - m) * rinv + pb[c];
        float z = b2s;
#pragma unroll
        for (int j = 0; j < 6; j++) {
            float t = b1[j];
#pragma unroll
            for (int c = 0; c < 9; c++) t += y[c] * w1[c][j];
            t = fmaxf(t, 0.f);
            z += t * w2[j];
        }
        float g = 1.f / (1.f + __expf(-z));
        long long o = ((long long)b * SS + i0 + ii) * SS + j0 + jj;
        mout[o] = matrix[o] * g;
    }
}

// ============================================================
// Final layernorm over 256 channels: one block per row
// ============================================================
__global__ __launch_bounds__(256) void ln_kernel(
    const float* __restrict__ x, const float* __restrict__ g,
    const float* __restrict__ bt, float* __restrict__ out)
{
    int row = blockIdx.x, tid = threadIdx.x;
    float v = x[(long long)row * DM + tid];

    __shared__ float red[8];
    float s = v;
#pragma unroll
    for (int o = 16; o; o >>= 1) s += __shfl_xor_sync(0xffffffffu, s, o);
    if ((tid & 31) == 0) red[tid >> 5] = s;
    __syncthreads();
    float tot = 0.f;
#pragma unroll
    for (int i = 0; i < 8; i++) tot += red[i];
    float m = tot * (1.f / DM);
    __syncthreads();

    float d = v - m;
    float s2 = d * d;
#pragma unroll
    for (int o = 16; o; o >>= 1) s2 += __shfl_xor_sync(0xffffffffu, s2, o);
    if ((tid & 31) == 0) red[tid >> 5] = s2;
    __syncthreads();
    float vtot = 0.f;
#pragma unroll
    for (int i = 0; i < 8; i++) vtot += red[i];
    float var = vtot * (1.f / DM);

    out[(long long)row * DM + tid] = g[tid] * d * rsqrtf(var + EPS) + bt[tid];
}

// ============================================================
extern "C" void kernel_launch(void* const* d_in, const int* in_sizes, int n_in,
                              void* d_out, int out_size)
{
    const float* inQ    = (const float*)d_in[0];
    const float* inK    = (const float*)d_in[1];
    const float* inV    = (const float*)d_in[2];
    const int*   mask   = (const int*)  d_in[3];
    const float* matrix = (const float*)d_in[4];
    const float* W_Q    = (const float*)d_in[5];
    const float* W_K    = (const float*)d_in[6];
    const float* W_V    = (const float*)d_in[7];
    const float* W_V2   = (const float*)d_in[8];
    const float* W_fc   = (const float*)d_in[9];
    const float* ln_g   = (const float*)d_in[10];
    const float* ln_b   = (const float*)d_in[11];
    const float* fu_ln_g= (const float*)d_in[12];
    const float* fu_ln_b= (const float*)d_in[13];
    const float* fu_w1  = (const float*)d_in[14];
    const float* fu_b1  = (const float*)d_in[15];
    const float* fu_w2  = (const float*)d_in[16];
    const float* fu_b2  = (const float*)d_in[17];

    float* out  = (float*)d_out;                            // [B,S,DM]
    float* mout = (float*)d_out + (long long)BB * SS * DM;  // [B,S,S]

    float *pQ, *pK, *pV, *pattn, *pvp2, *pctx, *pfc;
    cudaGetSymbolAddress((void**)&pQ, g_Q);
    cudaGetSymbolAddress((void**)&pK, g_K);
    cudaGetSymbolAddress((void**)&pV, g_V);
    cudaGetSymbolAddress((void**)&pattn, g_attn);
    cudaGetSymbolAddress((void**)&pvp2, g_vp2);
    cudaGetSymbolAddress((void**)&pctx, g_ctx);
    cudaGetSymbolAddress((void**)&pfc, g_fc);

    // (0) QKV projections in ONE launch (z-dispatch, single-buffered inner loop)
    sgemm2_kernel<<<dim3(4, 64, 3), 256>>>(inQ, inK, inV, W_Q, W_K, W_V,
                                           pQ, pK, pV, DM, DM, DM, DM);
    // (1) vp2 = input_V @ W_V2 : [8192,256] @ [256,32]
    sgemm_n32_kernel<<<dim3(1, 64), 256>>>(inV, W_V2, pvp2, DM, DM);

    // (2) fused attention (writes attn + ctx cols 0..255)
    attn2_kernel<<<dim3(SS / 16, HH, BB), 256>>>(pQ, pK, pV, mask, pattn, pctx);

    // (3) context2 = matrix @ vp2 -> ctx cols 256..287
    ctx2_kernel<<<dim3(16, BB), 256>>>(matrix, pvp2, pctx);

    // (4) fc: [8192,288] @ [288,256]
    sgemm2_kernel<<<dim3(4, 64, 1), 256>>>(pctx, pctx, pctx, W_fc, W_fc, W_fc,
                                           pfc, pfc, pfc, CTXW, CTXW, DM, DM);

    // (5) gate -> matrix_out  (launch index 5: captured by ncu -s 5 -c 1)
    gate_kernel<<<dim3(SS / 32, SS / 32, BB), 256>>>(pattn, matrix, mout,
                                                     fu_ln_g, fu_ln_b, fu_w1, fu_b1, fu_w2, fu_b2);

    // (6) final layernorm -> output
    ln_kernel<<<BB * SS, 256>>>(pfc, ln_g, ln_b, out);
}

// round 8
// speedup vs baseline: 2.0255x; 1.1089x over previous
#include <cuda_runtime.h>
#include <math.h>

// Problem constants
#define BB 16
#define SS 512
#define DM 256
#define HH 8
#define DKV 32
#define CTXW 288   // DV*(H+1)
#define EPS 1e-5f

// -------- scratch (device globals; no allocation allowed) --------
__device__ float g_Q[BB * SS * DM];
__device__ float g_K[BB * SS * DM];
__device__ float g_V[BB * SS * DM];
__device__ float g_attn[(long)BB * HH * SS * SS];   // 134 MB
__device__ float g_vp2[BB * SS * DKV];
__device__ float g_ctx[BB * SS * CTXW];
__device__ float g_fc[BB * SS * DM];

// ---- packed f32x2 FMA (Blackwell FFMA2; PTX-only, ptxas won't auto-fuse) ----
__device__ __forceinline__ void ffma2(float2 &d, const float2 &a, const float2 &b) {
    unsigned long long &dd = reinterpret_cast<unsigned long long &>(d);
    const unsigned long long &aa = reinterpret_cast<const unsigned long long &>(a);
    const unsigned long long &bb = reinterpret_cast<const unsigned long long &>(b);
    asm("fma.rn.f32x2 %0, %1, %2, %0;" : "+l"(dd) : "l"(aa), "l"(bb));
}

// ---- cp.async helpers (8-byte: keeps conflict-free stride-17 smem layout) ----
__device__ __forceinline__ void cp_async8(void* smem, const void* gmem) {
    unsigned saddr = (unsigned)__cvta_generic_to_shared(smem);
    asm volatile("cp.async.ca.shared.global [%0], [%1], 8;" :: "r"(saddr), "l"(gmem));
}
__device__ __forceinline__ void cp_commit() {
    asm volatile("cp.async.commit_group;" ::: "memory");
}
template<int N>
__device__ __forceinline__ void cp_wait() {
    asm volatile("cp.async.wait_group %0;" :: "n"(N) : "memory");
}

// ============================================================
// SGEMM v2 (single-buffered inner loop), z-dispatched over up to
// 3 independent (A,B,C) triples. tile 128x64, BK=16, 256 threads.
// ============================================================
__global__ __launch_bounds__(256) void sgemm2_kernel(
    const float* __restrict__ A0, const float* __restrict__ A1, const float* __restrict__ A2,
    const float* __restrict__ B0, const float* __restrict__ B1, const float* __restrict__ B2,
    float* __restrict__ C0, float* __restrict__ C1, float* __restrict__ C2,
    int K, int lda, int ldb, int ldc)
{
    const int z = blockIdx.z;
    const float* A = (z == 0) ? A0 : (z == 1) ? A1 : A2;
    const float* B = (z == 0) ? B0 : (z == 1) ? B1 : B2;
    float*       C = (z == 0) ? C0 : (z == 1) ? C1 : C2;

    __shared__ __align__(16) float As[16][130];  // [k][m], m contiguous
    __shared__ __align__(16) float Bs[16][68];   // [k][n]
    const int tid = threadIdx.x;
    const int tx = tid & 15, ty = tid >> 4;
    const int m0 = blockIdx.y * 128, n0 = blockIdx.x * 64;

    float2 acc[4][4];
#pragma unroll
    for (int i = 0; i < 4; i++)
#pragma unroll
        for (int j = 0; j < 4; j++) acc[i][j] = make_float2(0.f, 0.f);

    for (int k0 = 0; k0 < K; k0 += 16) {
#pragma unroll
        for (int t = 0; t < 2; t++) {
            int idx = tid + t * 256;
            int row = idx >> 2, kq = idx & 3;
            float4 v = *(const float4*)&A[(size_t)(m0 + row) * lda + k0 + kq * 4];
            As[kq * 4 + 0][row] = v.x; As[kq * 4 + 1][row] = v.y;
            As[kq * 4 + 2][row] = v.z; As[kq * 4 + 3][row] = v.w;
        }
        {
            int kk = tid >> 4, nq = tid & 15;
            *(float4*)&Bs[kk][nq * 4] =
                *(const float4*)&B[(size_t)(k0 + kk) * ldb + n0 + nq * 4];
        }
        __syncthreads();
#pragma unroll
        for (int kk = 0; kk < 16; kk++) {
            float2 a[4];
#pragma unroll
            for (int i = 0; i < 4; i++) a[i] = *(float2*)&As[kk][ty * 8 + 2 * i];
            float2 bA = *(float2*)&Bs[kk][tx * 4];
            float2 bB = *(float2*)&Bs[kk][tx * 4 + 2];
            float2 bj[4] = {{bA.x, bA.x}, {bA.y, bA.y}, {bB.x, bB.x}, {bB.y, bB.y}};
#pragma unroll
            for (int j = 0; j < 4; j++)
#pragma unroll
                for (int i = 0; i < 4; i++) ffma2(acc[i][j], a[i], bj[j]);
        }
        __syncthreads();
    }
#pragma unroll
    for (int i = 0; i < 4; i++) {
        int m = m0 + ty * 8 + 2 * i;
        float4 lo = {acc[i][0].x, acc[i][1].x, acc[i][2].x, acc[i][3].x};
        float4 hi = {acc[i][0].y, acc[i][1].y, acc[i][2].y, acc[i][3].y};
        *(float4*)&C[(size_t)m * ldc + n0 + tx * 4] = lo;
        *(float4*)&C[(size_t)(m + 1) * ldc + n0 + tx * 4] = hi;
    }
}

// ============================================================
// SGEMM narrow: N=32 (vp2 projection). tile 128x32, BK=16.
// ============================================================
__global__ __launch_bounds__(256) void sgemm_n32_kernel(
    const float* __restrict__ A, const float* __restrict__ B, float* __restrict__ C,
    int K, int lda)
{
    __shared__ __align__(16) float As[16][130];
    __shared__ __align__(16) float Bs[16][36];
    const int tid = threadIdx.x;
    const int tx = tid & 7, ty = tid >> 3;
    const int m0 = blockIdx.y * 128;

    float2 acc[2][4];
#pragma unroll
    for (int i = 0; i < 2; i++)
#pragma unroll
        for (int j = 0; j < 4; j++) acc[i][j] = make_float2(0.f, 0.f);

    for (int k0 = 0; k0 < K; k0 += 16) {
#pragma unroll
        for (int t = 0; t < 2; t++) {
            int idx = tid + t * 256;
            int row = idx >> 2, kq = idx & 3;
            float4 v = *(const float4*)&A[(size_t)(m0 + row) * lda + k0 + kq * 4];
            As[kq * 4 + 0][row] = v.x; As[kq * 4 + 1][row] = v.y;
            As[kq * 4 + 2][row] = v.z; As[kq * 4 + 3][row] = v.w;
        }
        if (tid < 128) {
            int kk = tid >> 3, nq = tid & 7;
            *(float4*)&Bs[kk][nq * 4] =
                *(const float4*)&B[(size_t)(k0 + kk) * DKV + nq * 4];
        }
        __syncthreads();
#pragma unroll
        for (int kk = 0; kk < 16; kk++) {
            float2 a0 = *(float2*)&As[kk][ty * 4];
            float2 a1 = *(float2*)&As[kk][ty * 4 + 2];
            float2 bA = *(float2*)&Bs[kk][tx * 4];
            float2 bB = *(float2*)&Bs[kk][tx * 4 + 2];
            float2 bj[4] = {{bA.x, bA.x}, {bA.y, bA.y}, {bB.x, bB.x}, {bB.y, bB.y}};
#pragma unroll
            for (int j = 0; j < 4; j++) { ffma2(acc[0][j], a0, bj[j]); ffma2(acc[1][j], a1, bj[j]); }
        }
        __syncthreads();
    }
#pragma unroll
    for (int i = 0; i < 2; i++) {
        int m = m0 + ty * 4 + 2 * i;
        float4 lo = {acc[i][0].x, acc[i][1].x, acc[i][2].x, acc[i][3].x};
        float4 hi = {acc[i][0].y, acc[i][1].y, acc[i][2].y, acc[i][3].y};
        *(float4*)&C[(size_t)m * DKV + tx * 4] = lo;
        *(float4*)&C[(size_t)(m + 1) * DKV + tx * 4] = hi;
    }
}

// ============================================================
// Fused attention v4: cp.async DOUBLE-BUFFERED K/V (no register
// pressure, unlike R5), mask prefetch overlapping wait, V chunk 0
// issued before softmax. grid (S/16, H, B), 256 threads.
// ============================================================
__global__ __launch_bounds__(256) void attn4_kernel(
    const float* __restrict__ Q, const float* __restrict__ K, const float* __restrict__ V,
    const int* __restrict__ mask, float* __restrict__ attn, float* __restrict__ ctx)
{
    const int q0 = blockIdx.x * 16;
    const int h = blockIdx.y;
    const int b = blockIdx.z;
    const int tid = threadIdx.x;
    const int lane = tid & 31, warp = tid >> 5;

    __shared__ __align__(16) float  Sb[16][528];        // bank-shifted rows
    __shared__ __align__(16) float2 KV2[2][64][17];     // double-buffered, conflict-free stride

    // ---- stage Q scaled (buf 0), pull own row into registers ----
    {
        int sq = tid >> 4, dp = tid & 15;
        float2 v = *(const float2*)&Q[((size_t)(b * SS + q0 + sq)) * DM + h * DKV + dp * 2];
        v.x *= 0.17677669529663687f; v.y *= 0.17677669529663687f;
        KV2[0][sq][dp] = v;
    }
    __syncthreads();
    const int qq = (warp << 1) | (lane >> 4);
    float2 qr[16];
#pragma unroll
    for (int dp = 0; dp < 16; dp++) qr[dp] = KV2[0][qq][dp];
    __syncthreads();

    const long long mrow0 = (((long long)(b * HH + h)) * SS + q0) * SS;
    const int lkk = tid >> 4, ldp = tid & 15;   // loader: 4 rows per thread (stride 16)
    const float* Kb = &K[((size_t)(b * SS)) * DM + h * DKV];
    const float* Vb = &V[((size_t)(b * SS)) * DM + h * DKV];

    // ---- scores + mask (cp.async double-buffered K) ----
    // prologue: K chunk 0 -> buf 0
#pragma unroll
    for (int t = 0; t < 4; t++)
        cp_async8(&KV2[0][lkk + t * 16][ldp], Kb + (size_t)(lkk + t * 16) * DM + ldp * 2);
    cp_commit();

    const int kb = lane & 15;
    for (int it = 0; it < 8; it++) {
        const int cur = it & 1;
        const int k0 = it * 64;
        if (it < 7) {
            const float* src = Kb + (size_t)(k0 + 64) * DM;
#pragma unroll
            for (int t = 0; t < 4; t++)
                cp_async8(&KV2[cur ^ 1][lkk + t * 16][ldp], src + (size_t)(lkk + t * 16) * DM + ldp * 2);
            cp_commit();
        }
        // mask prefetch (DRAM stream) overlaps the wait below
        int mk[4];
#pragma unroll
        for (int jj = 0; jj < 4; jj++)
            mk[jj] = mask[mrow0 + (long long)qq * SS + k0 + kb + jj * 16];
        if (it < 7) cp_wait<1>(); else cp_wait<0>();
        __syncthreads();
#pragma unroll
        for (int jj = 0; jj < 4; jj++) {
            int kk = kb + jj * 16;
            float2 acc = make_float2(0.f, 0.f);
#pragma unroll
            for (int dp = 0; dp < 16; dp++) ffma2(acc, qr[dp], KV2[cur][kk][dp]);
            Sb[qq][k0 + kk] = mk[jj] ? -1e9f : (acc.x + acc.y);
        }
        __syncthreads();
    }

    // ---- issue V chunk 0 now: softmax hides its latency ----
#pragma unroll
    for (int t = 0; t < 4; t++)
        cp_async8(&KV2[0][lkk + t * 16][ldp], Vb + (size_t)(lkk + t * 16) * DM + ldp * 2);
    cp_commit();

    // ---- softmax (warp-local rows 2w, 2w+1) + write attn ----
#pragma unroll
    for (int rr = 0; rr < 2; rr++) {
        int q = (warp << 1) | rr;
        float mx = -1e30f;
#pragma unroll
        for (int t = 0; t < 4; t++) {
            float4 v = *(float4*)&Sb[q][(lane + t * 32) * 4];
            mx = fmaxf(mx, fmaxf(fmaxf(v.x, v.y), fmaxf(v.z, v.w)));
        }
#pragma unroll
        for (int o = 16; o; o >>= 1) mx = fmaxf(mx, __shfl_xor_sync(0xffffffffu, mx, o));
        float sum = 0.f;
#pragma unroll
        for (int t = 0; t < 4; t++) {
            float4 v = *(float4*)&Sb[q][(lane + t * 32) * 4];
            v.x = __expf(v.x - mx); v.y = __expf(v.y - mx);
            v.z = __expf(v.z - mx); v.w = __expf(v.w - mx);
            *(float4*)&Sb[q][(lane + t * 32) * 4] = v;
            sum += v.x + v.y + v.z + v.w;
        }
#pragma unroll
        for (int o = 16; o; o >>= 1) sum += __shfl_xor_sync(0xffffffffu, sum, o);
        float inv = 1.f / sum;
        long long base = mrow0 + (long long)q * SS;
#pragma unroll
        for (int t = 0; t < 4; t++) {
            float4 v = *(float4*)&Sb[q][(lane + t * 32) * 4];
            v.x *= inv; v.y *= inv; v.z *= inv; v.w *= inv;
            *(float4*)&Sb[q][(lane + t * 32) * 4] = v;
            *(float4*)&attn[base + (lane + t * 32) * 4] = v;
        }
    }

    // ---- attn @ V (cp.async double-buffered V) ----
    {
        const int cq = tid >> 4, dp = tid & 15;
        float2 acc = make_float2(0.f, 0.f);
        for (int it = 0; it < 8; it++) {
            const int cur = it & 1;
            const int k0 = it * 64;
            if (it < 7) {
                const float* src = Vb + (size_t)(k0 + 64) * DM;
#pragma unroll
                for (int t = 0; t < 4; t++)
                    cp_async8(&KV2[cur ^ 1][lkk + t * 16][ldp], src + (size_t)(lkk + t * 16) * DM + ldp * 2);
                cp_commit();
            }
            if (it < 7) cp_wait<1>(); else cp_wait<0>();
            __syncthreads();   // at it=0 this also publishes softmax's Sb writes
#pragma unroll
            for (int kp = 0; kp < 32; kp++) {
                float2 ap = *(const float2*)&Sb[cq][k0 + 2 * kp];
                float2 a0 = {ap.x, ap.x}, a1 = {ap.y, ap.y};
                ffma2(acc, a0, KV2[cur][2 * kp][dp]);
                ffma2(acc, a1, KV2[cur][2 * kp + 1][dp]);
            }
            __syncthreads();
        }
        *(float2*)&ctx[((size_t)(b * SS + q0 + cq)) * CTXW + h * DKV + dp * 2] = acc;
    }
}

// ============================================================
// context2 = matrix @ vp2 -> ctx cols [256, 288).
// ============================================================
__global__ __launch_bounds__(256) void ctx2_kernel(
    const float* __restrict__ matrix, const float* __restrict__ vp2, float* __restrict__ ctx)
{
    __shared__ __align__(16) float  Ms[32][68];
    __shared__ __align__(16) float2 Vs[64][17];
    const int b = blockIdx.y, i0 = blockIdx.x * 32;
    const int tid = threadIdx.x;
    const int r = tid >> 3, cq = tid & 7;

    float2 acc0 = make_float2(0.f, 0.f), acc1 = make_float2(0.f, 0.f);
    for (int k0 = 0; k0 < SS; k0 += 64) {
#pragma unroll
        for (int t = 0; t < 2; t++) {
            int idx = tid + t * 256;
            int row = idx >> 4, c4 = idx & 15;
            *(float4*)&Ms[row][c4 * 4] =
                *(const float4*)&matrix[((size_t)(b * SS + i0 + row)) * SS + k0 + c4 * 4];
        }
#pragma unroll
        for (int t = 0; t < 4; t++) {
            int idx = tid + t * 256, kk = idx >> 4, dp = idx & 15;
            Vs[kk][dp] = *(const float2*)&vp2[((size_t)(b * SS + k0 + kk)) * DKV + dp * 2];
        }
        __syncthreads();
#pragma unroll
        for (int kk = 0; kk < 64; kk++) {
            float a = Ms[r][kk];
            float2 a2 = {a, a};
            ffma2(acc0, a2, Vs[kk][cq * 2]);
            ffma2(acc1, a2, Vs[kk][cq * 2 + 1]);
        }
        __syncthreads();
    }
    float4 o4 = {acc0.x, acc0.y, acc1.x, acc1.y};
    *(float4*)&ctx[((size_t)(b * SS + i0 + r)) * CTXW + HH * DKV + cq * 4] = o4;
}

// ============================================================
// Gate v2 (R6 winner): MLP-36 batched loads, LN -> relu -> sigmoid,
// matrix_out = matrix * g
// ============================================================
__global__ __launch_bounds__(256) void gate_kernel(
    const float* __restrict__ attn, const float* __restrict__ matrix, float* __restrict__ mout,
    const float* __restrict__ fu_ln_g, const float* __restrict__ fu_ln_b,
    const float* __restrict__ fu_w1, const float* __restrict__ fu_b1,
    const float* __restrict__ fu_w2, const float* __restrict__ fu_b2)
{
    __shared__ float pl[9][32][33];
    __shared__ float pg[9], pb[9], w1[9][6], b1[6], w2[6], b2s;

    int b = blockIdx.z;
    int i0 = blockIdx.y * 32, j0 = blockIdx.x * 32;
    int tid = threadIdx.x;

    if (tid < 9) { pg[tid] = fu_ln_g[tid]; pb[tid] = fu_ln_b[tid]; }
    if (tid >= 32 && tid < 86) { int t = tid - 32; w1[t / 6][t % 6] = fu_w1[t]; }
    if (tid >= 96 && tid < 102) b1[tid - 96] = fu_b1[tid - 96];
    if (tid >= 128 && tid < 134) w2[tid - 128] = fu_w2[tid - 128];
    if (tid == 160) b2s = fu_b2[0];

    {
        const int jj0 = tid >> 5, ii = tid & 31;
        const float* srcs[9];
        srcs[0] = matrix + (size_t)b * SS * SS;
#pragma unroll
        for (int c = 1; c < 9; c++)
            srcs[c] = attn + ((size_t)(b * HH + c - 1)) * SS * SS;

        float vals[9][4];
#pragma unroll
        for (int c = 0; c < 9; c++)
#pragma unroll
            for (int t = 0; t < 4; t++)
                vals[c][t] = srcs[c][(size_t)(j0 + jj0 + t * 8) * SS + i0 + ii];

#pragma unroll
        for (int c = 0; c < 9; c++)
#pragma unroll
            for (int t = 0; t < 4; t++)
                pl[c][jj0 + t * 8][ii] = vals[c][t];
    }
    __syncthreads();

#pragma unroll
    for (int r = 0; r < 4; r++) {
        int idx = tid + r * 256;
        int ii = idx >> 5, jj = idx & 31;
        float v[9];
        float m = 0.f;
#pragma unroll
        for (int c = 0; c < 9; c++) { v[c] = pl[c][jj][ii]; m += v[c]; }
        m *= (1.f / 9.f);
        float var = 0.f;
#pragma unroll
        for (int c = 0; c < 9; c++) { float dd = v[c] - m; var += dd * dd; }
        var *= (1.f / 9.f);
        float rinv = rsqrtf(var + EPS);
        float y[9];
#pragma unroll
        for (int c = 0; c < 9; c++) y[c] = pg[c] * (v[c] - m) * rinv + pb[c];
        float z = b2s;
#pragma unroll
        for (int j = 0; j < 6; j++) {
            float t = b1[j];
#pragma unroll
            for (int c = 0; c < 9; c++) t += y[c] * w1[c][j];
            t = fmaxf(t, 0.f);
            z += t * w2[j];
        }
        float g = 1.f / (1.f + __expf(-z));
        long long o = ((long long)b * SS + i0 + ii) * SS + j0 + jj;
        mout[o] = matrix[o] * g;
    }
}

// ============================================================
// Final layernorm over 256 channels: one block per row
// ============================================================
__global__ __launch_bounds__(256) void ln_kernel(
    const float* __restrict__ x, const float* __restrict__ g,
    const float* __restrict__ bt, float* __restrict__ out)
{
    int row = blockIdx.x, tid = threadIdx.x;
    float v = x[(long long)row * DM + tid];

    __shared__ float red[8];
    float s = v;
#pragma unroll
    for (int o = 16; o; o >>= 1) s += __shfl_xor_sync(0xffffffffu, s, o);
    if ((tid & 31) == 0) red[tid >> 5] = s;
    __syncthreads();
    float tot = 0.f;
#pragma unroll
    for (int i = 0; i < 8; i++) tot += red[i];
    float m = tot * (1.f / DM);
    __syncthreads();

    float d = v - m;
    float s2 = d * d;
#pragma unroll
    for (int o = 16; o; o >>= 1) s2 += __shfl_xor_sync(0xffffffffu, s2, o);
    if ((tid & 31) == 0) red[tid >> 5] = s2;
    __syncthreads();
    float vtot = 0.f;
#pragma unroll
    for (int i = 0; i < 8; i++) vtot += red[i];
    float var = vtot * (1.f / DM);

    out[(long long)row * DM + tid] = g[tid] * d * rsqrtf(var + EPS) + bt[tid];
}

// ============================================================
extern "C" void kernel_launch(void* const* d_in, const int* in_sizes, int n_in,
                              void* d_out, int out_size)
{
    const float* inQ    = (const float*)d_in[0];
    const float* inK    = (const float*)d_in[1];
    const float* inV    = (const float*)d_in[2];
    const int*   mask   = (const int*)  d_in[3];
    const float* matrix = (const float*)d_in[4];
    const float* W_Q    = (const float*)d_in[5];
    const float* W_K    = (const float*)d_in[6];
    const float* W_V    = (const float*)d_in[7];
    const float* W_V2   = (const float*)d_in[8];
    const float* W_fc   = (const float*)d_in[9];
    const float* ln_g   = (const float*)d_in[10];
    const float* ln_b   = (const float*)d_in[11];
    const float* fu_ln_g= (const float*)d_in[12];
    const float* fu_ln_b= (const float*)d_in[13];
    const float* fu_w1  = (const float*)d_in[14];
    const float* fu_b1  = (const float*)d_in[15];
    const float* fu_w2  = (const float*)d_in[16];
    const float* fu_b2  = (const float*)d_in[17];

    float* out  = (float*)d_out;                            // [B,S,DM]
    float* mout = (float*)d_out + (long long)BB * SS * DM;  // [B,S,S]

    float *pQ, *pK, *pV, *pattn, *pvp2, *pctx, *pfc;
    cudaGetSymbolAddress((void**)&pQ, g_Q);
    cudaGetSymbolAddress((void**)&pK, g_K);
    cudaGetSymbolAddress((void**)&pV, g_V);
    cudaGetSymbolAddress((void**)&pattn, g_attn);
    cudaGetSymbolAddress((void**)&pvp2, g_vp2);
    cudaGetSymbolAddress((void**)&pctx, g_ctx);
    cudaGetSymbolAddress((void**)&pfc, g_fc);

    // (0) QKV projections in ONE launch (z-dispatch)
    sgemm2_kernel<<<dim3(4, 64, 3), 256>>>(inQ, inK, inV, W_Q, W_K, W_V,
                                           pQ, pK, pV, DM, DM, DM, DM);
    // (1) vp2 = input_V @ W_V2
    sgemm_n32_kernel<<<dim3(1, 64), 256>>>(inV, W_V2, pvp2, DM, DM);

    // (2) fused attention (cp.async pipelined; writes attn + ctx cols 0..255)
    attn4_kernel<<<dim3(SS / 16, HH, BB), 256>>>(pQ, pK, pV, mask, pattn, pctx);

    // (3) context2 = matrix @ vp2 -> ctx cols 256..287
    ctx2_kernel<<<dim3(16, BB), 256>>>(matrix, pvp2, pctx);

    // (4) fc: [8192,288] @ [288,256]
    sgemm2_kernel<<<dim3(4, 64, 1), 256>>>(pctx, pctx, pctx, W_fc, W_fc, W_fc,
                                           pfc, pfc, pfc, CTXW, CTXW, DM, DM);

    // (5) gate -> matrix_out
    gate_kernel<<<dim3(SS / 32, SS / 32, BB), 256>>>(pattn, matrix, mout,
                                                     fu_ln_g, fu_ln_b, fu_w1, fu_b1, fu_w2, fu_b2);

    // (6) final layernorm -> output
    ln_kernel<<<BB * SS, 256>>>(pfc, ln_g, ln_b, out);
}

// round 10
// speedup vs baseline: 2.0653x; 1.0196x over previous
#include <cuda_runtime.h>
#include <cuda_fp16.h>
#include <math.h>

// Problem constants
#define BB 16
#define SS 512
#define DM 256
#define HH 8
#define DKV 32
#define CTXW 288   // DV*(H+1)
#define EPS 1e-5f

// -------- scratch (device globals; no allocation allowed) --------
__device__ float  g_Q[BB * SS * DM];
__device__ float  g_K[BB * SS * DM];
__device__ float  g_V[BB * SS * DM];
__device__ __half g_attn[(long)BB * HH * SS * SS];   // 67 MB (R8: fp16)
__device__ float  g_vp2[BB * SS * DKV];
__device__ float  g_ctx[BB * SS * CTXW];
__device__ float  g_fc[BB * SS * DM];

// ---- packed f32x2 FMA (Blackwell FFMA2; PTX-only, ptxas won't auto-fuse) ----
__device__ __forceinline__ void ffma2(float2 &d, const float2 &a, const float2 &b) {
    unsigned long long &dd = reinterpret_cast<unsigned long long &>(d);
    const unsigned long long &aa = reinterpret_cast<const unsigned long long &>(a);
    const unsigned long long &bb = reinterpret_cast<const unsigned long long &>(b);
    asm("fma.rn.f32x2 %0, %1, %2, %0;" : "+l"(dd) : "l"(aa), "l"(bb));
}

// ---- cp.async helpers (8-byte: keeps conflict-free stride-17 smem layout) ----
__device__ __forceinline__ void cp_async8(void* smem, const void* gmem) {
    unsigned saddr = (unsigned)__cvta_generic_to_shared(smem);
    asm volatile("cp.async.ca.shared.global [%0], [%1], 8;" :: "r"(saddr), "l"(gmem));
}
__device__ __forceinline__ void cp_commit() {
    asm volatile("cp.async.commit_group;" ::: "memory");
}
template<int N>
__device__ __forceinline__ void cp_wait() {
    asm volatile("cp.async.wait_group %0;" :: "n"(N) : "memory");
}

// ============================================================
// SGEMM v2 (single-buffered inner loop), z-dispatched over up to
// 3 independent (A,B,C) triples. tile 128x64, BK=16, 256 threads.
// ============================================================
__global__ __launch_bounds__(256) void sgemm2_kernel(
    const float* __restrict__ A0, const float* __restrict__ A1, const float* __restrict__ A2,
    const float* __restrict__ B0, const float* __restrict__ B1, const float* __restrict__ B2,
    float* __restrict__ C0, float* __restrict__ C1, float* __restrict__ C2,
    int K, int lda, int ldb, int ldc)
{
    const int z = blockIdx.z;
    const float* A = (z == 0) ? A0 : (z == 1) ? A1 : A2;
    const float* B = (z == 0) ? B0 : (z == 1) ? B1 : B2;
    float*       C = (z == 0) ? C0 : (z == 1) ? C1 : C2;

    __shared__ __align__(16) float As[16][130];  // [k][m], m contiguous
    __shared__ __align__(16) float Bs[16][68];   // [k][n]
    const int tid = threadIdx.x;
    const int tx = tid & 15, ty = tid >> 4;
    const int m0 = blockIdx.y * 128, n0 = blockIdx.x * 64;

    float2 acc[4][4];
#pragma unroll
    for (int i = 0; i < 4; i++)
#pragma unroll
        for (int j = 0; j < 4; j++) acc[i][j] = make_float2(0.f, 0.f);

    for (int k0 = 0; k0 < K; k0 += 16) {
#pragma unroll
        for (int t = 0; t < 2; t++) {
            int idx = tid + t * 256;
            int row = idx >> 2, kq = idx & 3;
            float4 v = *(const float4*)&A[(size_t)(m0 + row) * lda + k0 + kq * 4];
            As[kq * 4 + 0][row] = v.x; As[kq * 4 + 1][row] = v.y;
            As[kq * 4 + 2][row] = v.z; As[kq * 4 + 3][row] = v.w;
        }
        {
            int kk = tid >> 4, nq = tid & 15;
            *(float4*)&Bs[kk][nq * 4] =
                *(const float4*)&B[(size_t)(k0 + kk) * ldb + n0 + nq * 4];
        }
        __syncthreads();
#pragma unroll
        for (int kk = 0; kk < 16; kk++) {
            float2 a[4];
#pragma unroll
            for (int i = 0; i < 4; i++) a[i] = *(float2*)&As[kk][ty * 8 + 2 * i];
            float2 bA = *(float2*)&Bs[kk][tx * 4];
            float2 bB = *(float2*)&Bs[kk][tx * 4 + 2];
            float2 bj[4] = {{bA.x, bA.x}, {bA.y, bA.y}, {bB.x, bB.x}, {bB.y, bB.y}};
#pragma unroll
            for (int j = 0; j < 4; j++)
#pragma unroll
                for (int i = 0; i < 4; i++) ffma2(acc[i][j], a[i], bj[j]);
        }
        __syncthreads();
    }
#pragma unroll
    for (int i = 0; i < 4; i++) {
        int m = m0 + ty * 8 + 2 * i;
        float4 lo = {acc[i][0].x, acc[i][1].x, acc[i][2].x, acc[i][3].x};
        float4 hi = {acc[i][0].y, acc[i][1].y, acc[i][2].y, acc[i][3].y};
        *(float4*)&C[(size_t)m * ldc + n0 + tx * 4] = lo;
        *(float4*)&C[(size_t)(m + 1) * ldc + n0 + tx * 4] = hi;
    }
}

// ============================================================
// SGEMM narrow: N=32 (vp2 projection). tile 128x32, BK=16.
// ============================================================
__global__ __launch_bounds__(256) void sgemm_n32_kernel(
    const float* __restrict__ A, const float* __restrict__ B, float* __restrict__ C,
    int K, int lda)
{
    __shared__ __align__(16) float As[16][130];
    __shared__ __align__(16) float Bs[16][36];
    const int tid = threadIdx.x;
    const int tx = tid & 7, ty = tid >> 3;
    const int m0 = blockIdx.y * 128;

    float2 acc[2][4];
#pragma unroll
    for (int i = 0; i < 2; i++)
#pragma unroll
        for (int j = 0; j < 4; j++) acc[i][j] = make_float2(0.f, 0.f);

    for (int k0 = 0; k0 < K; k0 += 16) {
#pragma unroll
        for (int t = 0; t < 2; t++) {
            int idx = tid + t * 256;
            int row = idx >> 2, kq = idx & 3;
            float4 v = *(const float4*)&A[(size_t)(m0 + row) * lda + k0 + kq * 4];
            As[kq * 4 + 0][row] = v.x; As[kq * 4 + 1][row] = v.y;
            As[kq * 4 + 2][row] = v.z; As[kq * 4 + 3][row] = v.w;
        }
        if (tid < 128) {
            int kk = tid >> 3, nq = tid & 7;
            *(float4*)&Bs[kk][nq * 4] =
                *(const float4*)&B[(size_t)(k0 + kk) * DKV + nq * 4];
        }
        __syncthreads();
#pragma unroll
        for (int kk = 0; kk < 16; kk++) {
            float2 a0 = *(float2*)&As[kk][ty * 4];
            float2 a1 = *(float2*)&As[kk][ty * 4 + 2];
            float2 bA = *(float2*)&Bs[kk][tx * 4];
            float2 bB = *(float2*)&Bs[kk][tx * 4 + 2];
            float2 bj[4] = {{bA.x, bA.x}, {bA.y, bA.y}, {bB.x, bB.x}, {bB.y, bB.y}};
#pragma unroll
            for (int j = 0; j < 4; j++) { ffma2(acc[0][j], a0, bj[j]); ffma2(acc[1][j], a1, bj[j]); }
        }
        __syncthreads();
    }
#pragma unroll
    for (int i = 0; i < 2; i++) {
        int m = m0 + ty * 4 + 2 * i;
        float4 lo = {acc[i][0].x, acc[i][1].x, acc[i][2].x, acc[i][3].x};
        float4 hi = {acc[i][0].y, acc[i][1].y, acc[i][2].y, acc[i][3].y};
        *(float4*)&C[(size_t)m * DKV + tx * 4] = lo;
        *(float4*)&C[(size_t)(m + 1) * DKV + tx * 4] = hi;
    }
}

// ============================================================
// Fused attention v4 + fp16 attn store (R8). cp.async double-buffered
// K/V, mask prefetch overlapping wait, V chunk 0 issued before softmax.
// grid (S/16, H, B), 256 threads.
// ============================================================
__global__ __launch_bounds__(256) void attn4_kernel(
    const float* __restrict__ Q, const float* __restrict__ K, const float* __restrict__ V,
    const int* __restrict__ mask, __half* __restrict__ attn, float* __restrict__ ctx)
{
    const int q0 = blockIdx.x * 16;
    const int h = blockIdx.y;
    const int b = blockIdx.z;
    const int tid = threadIdx.x;
    const int lane = tid & 31, warp = tid >> 5;

    __shared__ __align__(16) float  Sb[16][528];        // bank-shifted rows
    __shared__ __align__(16) float2 KV2[2][64][17];     // double-buffered, conflict-free stride

    // ---- stage Q scaled (buf 0), pull own row into registers ----
    {
        int sq = tid >> 4, dp = tid & 15;
        float2 v = *(const float2*)&Q[((size_t)(b * SS + q0 + sq)) * DM + h * DKV + dp * 2];
        v.x *= 0.17677669529663687f; v.y *= 0.17677669529663687f;
        KV2[0][sq][dp] = v;
    }
    __syncthreads();
    const int qq = (warp << 1) | (lane >> 4);
    float2 qr[16];
#pragma unroll
    for (int dp = 0; dp < 16; dp++) qr[dp] = KV2[0][qq][dp];
    __syncthreads();

    const long long mrow0 = (((long long)(b * HH + h)) * SS + q0) * SS;
    const int lkk = tid >> 4, ldp = tid & 15;   // loader: 4 rows per thread (stride 16)
    const float* Kb = &K[((size_t)(b * SS)) * DM + h * DKV];
    const float* Vb = &V[((size_t)(b * SS)) * DM + h * DKV];

    // ---- scores + mask (cp.async double-buffered K) ----
#pragma unroll
    for (int t = 0; t < 4; t++)
        cp_async8(&KV2[0][lkk + t * 16][ldp], Kb + (size_t)(lkk + t * 16) * DM + ldp * 2);
    cp_commit();

    const int kb = lane & 15;
    for (int it = 0; it < 8; it++) {
        const int cur = it & 1;
        const int k0 = it * 64;
        if (it < 7) {
            const float* src = Kb + (size_t)(k0 + 64) * DM;
#pragma unroll
            for (int t = 0; t < 4; t++)
                cp_async8(&KV2[cur ^ 1][lkk + t * 16][ldp], src + (size_t)(lkk + t * 16) * DM + ldp * 2);
            cp_commit();
        }
        // mask prefetch (DRAM stream) overlaps the wait below
        int mk[4];
#pragma unroll
        for (int jj = 0; jj < 4; jj++)
            mk[jj] = mask[mrow0 + (long long)qq * SS + k0 + kb + jj * 16];
        if (it < 7) cp_wait<1>(); else cp_wait<0>();
        __syncthreads();
#pragma unroll
        for (int jj = 0; jj < 4; jj++) {
            int kk = kb + jj * 16;
            float2 acc = make_float2(0.f, 0.f);
#pragma unroll
            for (int dp = 0; dp < 16; dp++) ffma2(acc, qr[dp], KV2[cur][kk][dp]);
            Sb[qq][k0 + kk] = mk[jj] ? -1e9f : (acc.x + acc.y);
        }
        __syncthreads();
    }

    // ---- issue V chunk 0 now: softmax hides its latency ----
#pragma unroll
    for (int t = 0; t < 4; t++)
        cp_async8(&KV2[0][lkk + t * 16][ldp], Vb + (size_t)(lkk + t * 16) * DM + ldp * 2);
    cp_commit();

    // ---- softmax (warp-local rows 2w, 2w+1) + fp16 attn write ----
#pragma unroll
    for (int rr = 0; rr < 2; rr++) {
        int q = (warp << 1) | rr;
        float mx = -1e30f;
#pragma unroll
        for (int t = 0; t < 4; t++) {
            float4 v = *(float4*)&Sb[q][(lane + t * 32) * 4];
            mx = fmaxf(mx, fmaxf(fmaxf(v.x, v.y), fmaxf(v.z, v.w)));
        }
#pragma unroll
        for (int o = 16; o; o >>= 1) mx = fmaxf(mx, __shfl_xor_sync(0xffffffffu, mx, o));
        float sum = 0.f;
#pragma unroll
        for (int t = 0; t < 4; t++) {
            float4 v = *(float4*)&Sb[q][(lane + t * 32) * 4];
            v.x = __expf(v.x - mx); v.y = __expf(v.y - mx);
            v.z = __expf(v.z - mx); v.w = __expf(v.w - mx);
            *(float4*)&Sb[q][(lane + t * 32) * 4] = v;
            sum += v.x + v.y + v.z + v.w;
        }
#pragma unroll
        for (int o = 16; o; o >>= 1) sum += __shfl_xor_sync(0xffffffffu, sum, o);
        float inv = 1.f / sum;
        long long base = mrow0 + (long long)q * SS;
#pragma unroll
        for (int t = 0; t < 4; t++) {
            float4 v = *(float4*)&Sb[q][(lane + t * 32) * 4];
            v.x *= inv; v.y *= inv; v.z *= inv; v.w *= inv;
            *(float4*)&Sb[q][(lane + t * 32) * 4] = v;
            __half2 h0 = __floats2half2_rn(v.x, v.y);
            __half2 h1 = __floats2half2_rn(v.z, v.w);
            uint2 packed = { *(unsigned*)&h0, *(unsigned*)&h1 };
            *(uint2*)&attn[base + (lane + t * 32) * 4] = packed;   // 8B aligned
        }
    }

    // ---- attn @ V (cp.async double-buffered V) ----
    {
        const int cq = tid >> 4, dp = tid & 15;
        float2 acc = make_float2(0.f, 0.f);
        for (int it = 0; it < 8; it++) {
            const int cur = it & 1;
            const int k0 = it * 64;
            if (it < 7) {
                const float* src = Vb + (size_t)(k0 + 64) * DM;
#pragma unroll
                for (int t = 0; t < 4; t++)
                    cp_async8(&KV2[cur ^ 1][lkk + t * 16][ldp], src + (size_t)(lkk + t * 16) * DM + ldp * 2);
                cp_commit();
            }
            if (it < 7) cp_wait<1>(); else cp_wait<0>();
            __syncthreads();   // at it=0 this also publishes softmax's Sb writes
#pragma unroll
            for (int kp = 0; kp < 32; kp++) {
                float2 ap = *(const float2*)&Sb[cq][k0 + 2 * kp];
                float2 a0 = {ap.x, ap.x}, a1 = {ap.y, ap.y};
                ffma2(acc, a0, KV2[cur][2 * kp][dp]);
                ffma2(acc, a1, KV2[cur][2 * kp + 1][dp]);
            }
            __syncthreads();
        }
        *(float2*)&ctx[((size_t)(b * SS + q0 + cq)) * CTXW + h * DKV + dp * 2] = acc;
    }
}

// ============================================================
// context2 = matrix @ vp2 -> ctx cols [256, 288).
// ============================================================
__global__ __launch_bounds__(256) void ctx2_kernel(
    const float* __restrict__ matrix, const float* __restrict__ vp2, float* __restrict__ ctx)
{
    __shared__ __align__(16) float  Ms[32][68];
    __shared__ __align__(16) float2 Vs[64][17];
    const int b = blockIdx.y, i0 = blockIdx.x * 32;
    const int tid = threadIdx.x;
    const int r = tid >> 3, cq = tid & 7;

    float2 acc0 = make_float2(0.f, 0.f), acc1 = make_float2(0.f, 0.f);
    for (int k0 = 0; k0 < SS; k0 += 64) {
#pragma unroll
        for (int t = 0; t < 2; t++) {
            int idx = tid + t * 256;
            int row = idx >> 4, c4 = idx & 15;
            *(float4*)&Ms[row][c4 * 4] =
                *(const float4*)&matrix[((size_t)(b * SS + i0 + row)) * SS + k0 + c4 * 4];
        }
#pragma unroll
        for (int t = 0; t < 4; t++) {
            int idx = tid + t * 256, kk = idx >> 4, dp = idx & 15;
            Vs[kk][dp] = *(const float2*)&vp2[((size_t)(b * SS + k0 + kk)) * DKV + dp * 2];
        }
        __syncthreads();
#pragma unroll
        for (int kk = 0; kk < 64; kk++) {
            float a = Ms[r][kk];
            float2 a2 = {a, a};
            ffma2(acc0, a2, Vs[kk][cq * 2]);
            ffma2(acc1, a2, Vs[kk][cq * 2 + 1]);
        }
        __syncthreads();
    }
    float4 o4 = {acc0.x, acc0.y, acc1.x, acc1.y};
    *(float4*)&ctx[((size_t)(b * SS + i0 + r)) * CTXW + HH * DKV + cq * 4] = o4;
}

// ============================================================
// Gate v3 (R8): attn read as fp16, MLP-36 batched loads,
// LN -> relu -> sigmoid; matrix_out = matrix * g
// ============================================================
__global__ __launch_bounds__(256) void gate_kernel(
    const __half* __restrict__ attn, const float* __restrict__ matrix, float* __restrict__ mout,
    const float* __restrict__ fu_ln_g, const float* __restrict__ fu_ln_b,
    const float* __restrict__ fu_w1, const float* __restrict__ fu_b1,
    const float* __restrict__ fu_w2, const float* __restrict__ fu_b2)
{
    __shared__ float pl[9][32][33];
    __shared__ float pg[9], pb[9], w1[9][6], b1[6], w2[6], b2s;

    int b = blockIdx.z;
    int i0 = blockIdx.y * 32, j0 = blockIdx.x * 32;
    int tid = threadIdx.x;

    if (tid < 9) { pg[tid] = fu_ln_g[tid]; pb[tid] = fu_ln_b[tid]; }
    if (tid >= 32 && tid < 86) { int t = tid - 32; w1[t / 6][t % 6] = fu_w1[t]; }
    if (tid >= 96 && tid < 102) b1[tid - 96] = fu_b1[tid - 96];
    if (tid >= 128 && tid < 134) w2[tid - 128] = fu_w2[tid - 128];
    if (tid == 160) b2s = fu_b2[0];

    // ---- all loads batched first (1 fp32 plane + 8 fp16 planes x 4 rows) ----
    {
        const int jj0 = tid >> 5, ii = tid & 31;
        const float* msrc = matrix + (size_t)b * SS * SS;
        const __half* asrc[8];
#pragma unroll
        for (int c = 0; c < 8; c++)
            asrc[c] = attn + ((size_t)(b * HH + c)) * SS * SS;

        float  mval[4];
        __half aval[8][4];
#pragma unroll
        for (int t = 0; t < 4; t++)
            mval[t] = msrc[(size_t)(j0 + jj0 + t * 8) * SS + i0 + ii];
#pragma unroll
        for (int c = 0; c < 8; c++)
#pragma unroll
            for (int t = 0; t < 4; t++)
                aval[c][t] = asrc[c][(size_t)(j0 + jj0 + t * 8) * SS + i0 + ii];

#pragma unroll
        for (int t = 0; t < 4; t++)
            pl[0][jj0 + t * 8][ii] = mval[t];
#pragma unroll
        for (int c = 0; c < 8; c++)
#pragma unroll
            for (int t = 0; t < 4; t++)
                pl[c + 1][jj0 + t * 8][ii] = __half2float(aval[c][t]);
    }
    __syncthreads();

#pragma unroll
    for (int r = 0; r < 4; r++) {
        int idx = tid + r * 256;
        int ii = idx >> 5, jj = idx & 31;
        float v[9];
        float m = 0.f;
#pragma unroll
        for (int c = 0; c < 9; c++) { v[c] = pl[c][jj][ii]; m += v[c]; }
        m *= (1.f / 9.f);
        float var = 0.f;
#pragma unroll
        for (int c = 0; c < 9; c++) { float dd = v[c] - m; var += dd * dd; }
        var *= (1.f / 9.f);
        float rinv = rsqrtf(var + EPS);
        float y[9];
#pragma unroll
        for (int c = 0; c < 9; c++) y[c] = pg[c] * (v[c] - m) * rinv + pb[c];
        float z = b2s;
#pragma unroll
        for (int j = 0; j < 6; j++) {
            float t = b1[j];
#pragma unroll
            for (int c = 0; c < 9; c++) t += y[c] * w1[c][j];
            t = fmaxf(t, 0.f);
            z += t * w2[j];
        }
        float g = 1.f / (1.f + __expf(-z));
        long long o = ((long long)b * SS + i0 + ii) * SS + j0 + jj;
        mout[o] = matrix[o] * g;
    }
}

// ============================================================
// Final layernorm over 256 channels: one block per row
// ============================================================
__global__ __launch_bounds__(256) void ln_kernel(
    const float* __restrict__ x, const float* __restrict__ g,
    const float* __restrict__ bt, float* __restrict__ out)
{
    int row = blockIdx.x, tid = threadIdx.x;
    float v = x[(long long)row * DM + tid];

    __shared__ float red[8];
    float s = v;
#pragma unroll
    for (int o = 16; o; o >>= 1) s += __shfl_xor_sync(0xffffffffu, s, o);
    if ((tid & 31) == 0) red[tid >> 5] = s;
    __syncthreads();
    float tot = 0.f;
#pragma unroll
    for (int i = 0; i < 8; i++) tot += red[i];
    float m = tot * (1.f / DM);
    __syncthreads();

    float d = v - m;
    float s2 = d * d;
#pragma unroll
    for (int o = 16; o; o >>= 1) s2 += __shfl_xor_sync(0xffffffffu, s2, o);
    if ((tid & 31) == 0) red[tid >> 5] = s2;
    __syncthreads();
    float vtot = 0.f;
#pragma unroll
    for (int i = 0; i < 8; i++) vtot += red[i];
    float var = vtot * (1.f / DM);

    out[(long long)row * DM + tid] = g[tid] * d * rsqrtf(var + EPS) + bt[tid];
}

// ============================================================
extern "C" void kernel_launch(void* const* d_in, const int* in_sizes, int n_in,
                              void* d_out, int out_size)
{
    const float* inQ    = (const float*)d_in[0];
    const float* inK    = (const float*)d_in[1];
    const float* inV    = (const float*)d_in[2];
    const int*   mask   = (const int*)  d_in[3];
    const float* matrix = (const float*)d_in[4];
    const float* W_Q    = (const float*)d_in[5];
    const float* W_K    = (const float*)d_in[6];
    const float* W_V    = (const float*)d_in[7];
    const float* W_V2   = (const float*)d_in[8];
    const float* W_fc   = (const float*)d_in[9];
    const float* ln_g   = (const float*)d_in[10];
    const float* ln_b   = (const float*)d_in[11];
    const float* fu_ln_g= (const float*)d_in[12];
    const float* fu_ln_b= (const float*)d_in[13];
    const float* fu_w1  = (const float*)d_in[14];
    const float* fu_b1  = (const float*)d_in[15];
    const float* fu_w2  = (const float*)d_in[16];
    const float* fu_b2  = (const float*)d_in[17];

    float* out  = (float*)d_out;                            // [B,S,DM]
    float* mout = (float*)d_out + (long long)BB * SS * DM;  // [B,S,S]

    float *pQ, *pK, *pV, *pvp2, *pctx, *pfc;
    __half* pattn;
    cudaGetSymbolAddress((void**)&pQ, g_Q);
    cudaGetSymbolAddress((void**)&pK, g_K);
    cudaGetSymbolAddress((void**)&pV, g_V);
    cudaGetSymbolAddress((void**)&pattn, g_attn);
    cudaGetSymbolAddress((void**)&pvp2, g_vp2);
    cudaGetSymbolAddress((void**)&pctx, g_ctx);
    cudaGetSymbolAddress((void**)&pfc, g_fc);

    // (0) QKV projections in ONE launch (z-dispatch)
    sgemm2_kernel<<<dim3(4, 64, 3), 256>>>(inQ, inK, inV, W_Q, W_K, W_V,
                                           pQ, pK, pV, DM, DM, DM, DM);
    // (1) vp2 = input_V @ W_V2
    sgemm_n32_kernel<<<dim3(1, 64), 256>>>(inV, W_V2, pvp2, DM, DM);

    // (2) fused attention (cp.async pipelined; writes fp16 attn + ctx cols 0..255)
    attn4_kernel<<<dim3(SS / 16, HH, BB), 256>>>(pQ, pK, pV, mask, pattn, pctx);

    // (3) context2 = matrix @ vp2 -> ctx cols 256..287
    ctx2_kernel<<<dim3(16, BB), 256>>>(matrix, pvp2, pctx);

    // (4) fc: [8192,288] @ [288,256]
    sgemm2_kernel<<<dim3(4, 64, 1), 256>>>(pctx, pctx, pctx, W_fc, W_fc, W_fc,
                                           pfc, pfc, pfc, CTXW, CTXW, DM, DM);

    // (5) gate -> matrix_out
    gate_kernel<<<dim3(SS / 32, SS / 32, BB), 256>>>(pattn, matrix, mout,
                                                     fu_ln_g, fu_ln_b, fu_w1, fu_b1, fu_w2, fu_b2);

    // (6) final layernorm -> output
    ln_kernel<<<BB * SS, 256>>>(pfc, ln_g, ln_b, out);
}

// round 11
// speedup vs baseline: 2.5613x; 1.2402x over previous
#include <cuda_runtime.h>
#include <cuda_fp16.h>
#include <math.h>

// Problem constants
#define BB 16
#define SS 512
#define DM 256
#define HH 8
#define DKV 32
#define CTXW 288   // DV*(H+1)
#define EPS 1e-5f

// -------- scratch (device globals; no allocation allowed) --------
__device__ float  g_Q[BB * SS * DM];
__device__ float  g_K[BB * SS * DM];
__device__ float  g_V[BB * SS * DM];
__device__ __half g_attn[(long)BB * HH * SS * SS];   // 67 MB (fp16)
__device__ float  g_vp2[BB * SS * DKV];
__device__ float  g_ctx[BB * SS * CTXW];
__device__ float  g_fc[BB * SS * DM];

// ---- packed f32x2 FMA (Blackwell FFMA2; PTX-only, ptxas won't auto-fuse) ----
__device__ __forceinline__ void ffma2(float2 &d, const float2 &a, const float2 &b) {
    unsigned long long &dd = reinterpret_cast<unsigned long long &>(d);
    const unsigned long long &aa = reinterpret_cast<const unsigned long long &>(a);
    const unsigned long long &bb = reinterpret_cast<const unsigned long long &>(b);
    asm("fma.rn.f32x2 %0, %1, %2, %0;" : "+l"(dd) : "l"(aa), "l"(bb));
}

// ---- cp.async helpers (8-byte: keeps conflict-free stride-17 smem layout) ----
__device__ __forceinline__ void cp_async8(void* smem, const void* gmem) {
    unsigned saddr = (unsigned)__cvta_generic_to_shared(smem);
    asm volatile("cp.async.ca.shared.global [%0], [%1], 8;" :: "r"(saddr), "l"(gmem));
}
__device__ __forceinline__ void cp_commit() {
    asm volatile("cp.async.commit_group;" ::: "memory");
}
template<int N>
__device__ __forceinline__ void cp_wait() {
    asm volatile("cp.async.wait_group %0;" :: "n"(N) : "memory");
}

// dynamic smem size for attn5: Sb[32][528] f32 + KV2[2][64][17] float2
#define ATTN_SMEM (32 * 528 * 4 + 2 * 64 * 17 * 8)

// ============================================================
// SGEMM v2 (single-buffered inner loop), z-dispatched over up to
// 3 independent (A,B,C) triples. tile 128x64, BK=16, 256 threads.
// ============================================================
__global__ __launch_bounds__(256) void sgemm2_kernel(
    const float* __restrict__ A0, const float* __restrict__ A1, const float* __restrict__ A2,
    const float* __restrict__ B0, const float* __restrict__ B1, const float* __restrict__ B2,
    float* __restrict__ C0, float* __restrict__ C1, float* __restrict__ C2,
    int K, int lda, int ldb, int ldc)
{
    const int z = blockIdx.z;
    const float* A = (z == 0) ? A0 : (z == 1) ? A1 : A2;
    const float* B = (z == 0) ? B0 : (z == 1) ? B1 : B2;
    float*       C = (z == 0) ? C0 : (z == 1) ? C1 : C2;

    __shared__ __align__(16) float As[16][130];  // [k][m], m contiguous
    __shared__ __align__(16) float Bs[16][68];   // [k][n]
    const int tid = threadIdx.x;
    const int tx = tid & 15, ty = tid >> 4;
    const int m0 = blockIdx.y * 128, n0 = blockIdx.x * 64;

    float2 acc[4][4];
#pragma unroll
    for (int i = 0; i < 4; i++)
#pragma unroll
        for (int j = 0; j < 4; j++) acc[i][j] = make_float2(0.f, 0.f);

    for (int k0 = 0; k0 < K; k0 += 16) {
#pragma unroll
        for (int t = 0; t < 2; t++) {
            int idx = tid + t * 256;
            int row = idx >> 2, kq = idx & 3;
            float4 v = *(const float4*)&A[(size_t)(m0 + row) * lda + k0 + kq * 4];
            As[kq * 4 + 0][row] = v.x; As[kq * 4 + 1][row] = v.y;
            As[kq * 4 + 2][row] = v.z; As[kq * 4 + 3][row] = v.w;
        }
        {
            int kk = tid >> 4, nq = tid & 15;
            *(float4*)&Bs[kk][nq * 4] =
                *(const float4*)&B[(size_t)(k0 + kk) * ldb + n0 + nq * 4];
        }
        __syncthreads();
#pragma unroll
        for (int kk = 0; kk < 16; kk++) {
            float2 a[4];
#pragma unroll
            for (int i = 0; i < 4; i++) a[i] = *(float2*)&As[kk][ty * 8 + 2 * i];
            float2 bA = *(float2*)&Bs[kk][tx * 4];
            float2 bB = *(float2*)&Bs[kk][tx * 4 + 2];
            float2 bj[4] = {{bA.x, bA.x}, {bA.y, bA.y}, {bB.x, bB.x}, {bB.y, bB.y}};
#pragma unroll
            for (int j = 0; j < 4; j++)
#pragma unroll
                for (int i = 0; i < 4; i++) ffma2(acc[i][j], a[i], bj[j]);
        }
        __syncthreads();
    }
#pragma unroll
    for (int i = 0; i < 4; i++) {
        int m = m0 + ty * 8 + 2 * i;
        float4 lo = {acc[i][0].x, acc[i][1].x, acc[i][2].x, acc[i][3].x};
        float4 hi = {acc[i][0].y, acc[i][1].y, acc[i][2].y, acc[i][3].y};
        *(float4*)&C[(size_t)m * ldc + n0 + tx * 4] = lo;
        *(float4*)&C[(size_t)(m + 1) * ldc + n0 + tx * 4] = hi;
    }
}

// ============================================================
// SGEMM narrow: N=32 (vp2 projection). tile 128x32, BK=16.
// ============================================================
__global__ __launch_bounds__(256) void sgemm_n32_kernel(
    const float* __restrict__ A, const float* __restrict__ B, float* __restrict__ C,
    int K, int lda)
{
    __shared__ __align__(16) float As[16][130];
    __shared__ __align__(16) float Bs[16][36];
    const int tid = threadIdx.x;
    const int tx = tid & 7, ty = tid >> 3;
    const int m0 = blockIdx.y * 128;

    float2 acc[2][4];
#pragma unroll
    for (int i = 0; i < 2; i++)
#pragma unroll
        for (int j = 0; j < 4; j++) acc[i][j] = make_float2(0.f, 0.f);

    for (int k0 = 0; k0 < K; k0 += 16) {
#pragma unroll
        for (int t = 0; t < 2; t++) {
            int idx = tid + t * 256;
            int row = idx >> 2, kq = idx & 3;
            float4 v = *(const float4*)&A[(size_t)(m0 + row) * lda + k0 + kq * 4];
            As[kq * 4 + 0][row] = v.x; As[kq * 4 + 1][row] = v.y;
            As[kq * 4 + 2][row] = v.z; As[kq * 4 + 3][row] = v.w;
        }
        if (tid < 128) {
            int kk = tid >> 3, nq = tid & 7;
            *(float4*)&Bs[kk][nq * 4] =
                *(const float4*)&B[(size_t)(k0 + kk) * DKV + nq * 4];
        }
        __syncthreads();
#pragma unroll
        for (int kk = 0; kk < 16; kk++) {
            float2 a0 = *(float2*)&As[kk][ty * 4];
            float2 a1 = *(float2*)&As[kk][ty * 4 + 2];
            float2 bA = *(float2*)&Bs[kk][tx * 4];
            float2 bB = *(float2*)&Bs[kk][tx * 4 + 2];
            float2 bj[4] = {{bA.x, bA.x}, {bA.y, bA.y}, {bB.x, bB.x}, {bB.y, bB.y}};
#pragma unroll
            for (int j = 0; j < 4; j++) { ffma2(acc[0][j], a0, bj[j]); ffma2(acc[1][j], a1, bj[j]); }
        }
        __syncthreads();
    }
#pragma unroll
    for (int i = 0; i < 2; i++) {
        int m = m0 + ty * 4 + 2 * i;
        float4 lo = {acc[i][0].x, acc[i][1].x, acc[i][2].x, acc[i][3].x};
        float4 hi = {acc[i][0].y, acc[i][1].y, acc[i][2].y, acc[i][3].y};
        *(float4*)&C[(size_t)m * DKV + tx * 4] = lo;
        *(float4*)&C[(size_t)(m + 1) * DKV + tx * 4] = hi;
    }
}

// ============================================================
// Fused attention v5 (R10): 32-q-row tile, 2 q-rows per thread
// (every K/V shared load feeds 2 FFMA2), cp.async double-buffered
// K/V, fp16 attn store. Dynamic smem (85 KB), 2 blocks/SM.
// grid (S/32, H, B), 256 threads.
// ============================================================
__global__ __launch_bounds__(256, 2) void attn5_kernel(
    const float* __restrict__ Q, const float* __restrict__ K, const float* __restrict__ V,
    const int* __restrict__ mask, __half* __restrict__ attn, float* __restrict__ ctx)
{
    extern __shared__ __align__(16) char smem_raw[];
    float  (*Sb)[528]      = reinterpret_cast<float (*)[528]>(smem_raw);             // [32][528]
    float2 (*KV2)[64][17]  = reinterpret_cast<float2 (*)[64][17]>(smem_raw + 32 * 528 * 4); // [2][64][17]

    const int q0 = blockIdx.x * 32;
    const int h = blockIdx.y;
    const int b = blockIdx.z;
    const int tid = threadIdx.x;
    const int lane = tid & 31, warp = tid >> 5;

    const float* Qb = &Q[((size_t)(b * SS + q0)) * DM + h * DKV];
    const float* Kb = &K[((size_t)(b * SS)) * DM + h * DKV];
    const float* Vb = &V[((size_t)(b * SS)) * DM + h * DKV];
    const long long mrow0 = (((long long)(b * HH + h)) * SS + q0) * SS;

    const int lkk = tid >> 4, ldp = tid & 15;   // cp.async loader mapping

    // ---- issue K chunk 0 -> buf 0 immediately ----
#pragma unroll
    for (int t = 0; t < 4; t++)
        cp_async8(&KV2[0][lkk + t * 16][ldp], Kb + (size_t)(lkk + t * 16) * DM + ldp * 2);
    cp_commit();

    // ---- stage scaled Q (32x16 float2) into KV2[1], then to registers ----
    {
        int sq = tid >> 3, dq = tid & 7;
#pragma unroll
        for (int t = 0; t < 2; t++) {
            int dp = dq + t * 8;
            float2 v = *(const float2*)&Qb[(size_t)sq * DM + dp * 2];
            v.x *= 0.17677669529663687f; v.y *= 0.17677669529663687f;
            KV2[1][sq][dp] = v;
        }
    }
    __syncthreads();
    const int p  = (warp << 1) | (lane >> 4);   // 0..15 row-pair id
    const int qA = p, qB = p + 16;
    float2 qrA[16], qrB[16];
#pragma unroll
    for (int dp = 0; dp < 16; dp++) { qrA[dp] = KV2[1][qA][dp]; qrB[dp] = KV2[1][qB][dp]; }
    __syncthreads();   // all Q reads done before it=0 prefetch overwrites buf 1

    // ---- scores + mask (2 q-rows per thread) ----
    const int kb = lane & 15;
    const long long mrowA = mrow0 + (long long)qA * SS;
    const long long mrowB = mrow0 + (long long)qB * SS;
    for (int it = 0; it < 8; it++) {
        const int cur = it & 1;
        const int k0 = it * 64;
        if (it < 7) {
            const float* src = Kb + (size_t)(k0 + 64) * DM;
#pragma unroll
            for (int t = 0; t < 4; t++)
                cp_async8(&KV2[cur ^ 1][lkk + t * 16][ldp], src + (size_t)(lkk + t * 16) * DM + ldp * 2);
            cp_commit();
        }
        int mkA[4], mkB[4];
#pragma unroll
        for (int jj = 0; jj < 4; jj++) {
            mkA[jj] = mask[mrowA + k0 + kb + jj * 16];
            mkB[jj] = mask[mrowB + k0 + kb + jj * 16];
        }
        if (it < 7) cp_wait<1>(); else cp_wait<0>();
        __syncthreads();
#pragma unroll
        for (int jj = 0; jj < 4; jj++) {
            int kk = kb + jj * 16;
            float2 aA = make_float2(0.f, 0.f), aB = make_float2(0.f, 0.f);
#pragma unroll
            for (int dp = 0; dp < 16; dp++) {
                float2 v = KV2[cur][kk][dp];
                ffma2(aA, qrA[dp], v);
                ffma2(aB, qrB[dp], v);
            }
            Sb[qA][k0 + kk] = mkA[jj] ? -1e9f : (aA.x + aA.y);
            Sb[qB][k0 + kk] = mkB[jj] ? -1e9f : (aB.x + aB.y);
        }
        __syncthreads();
    }

    // ---- issue V chunk 0 now: softmax hides its latency ----
#pragma unroll
    for (int t = 0; t < 4; t++)
        cp_async8(&KV2[0][lkk + t * 16][ldp], Vb + (size_t)(lkk + t * 16) * DM + ldp * 2);
    cp_commit();

    // ---- softmax (4 rows per warp) + fp16 attn write ----
#pragma unroll
    for (int rr = 0; rr < 4; rr++) {
        int q = warp * 4 + rr;
        float mx = -1e30f;
#pragma unroll
        for (int t = 0; t < 4; t++) {
            float4 v = *(float4*)&Sb[q][(lane + t * 32) * 4];
            mx = fmaxf(mx, fmaxf(fmaxf(v.x, v.y), fmaxf(v.z, v.w)));
        }
#pragma unroll
        for (int o = 16; o; o >>= 1) mx = fmaxf(mx, __shfl_xor_sync(0xffffffffu, mx, o));
        float sum = 0.f;
#pragma unroll
        for (int t = 0; t < 4; t++) {
            float4 v = *(float4*)&Sb[q][(lane + t * 32) * 4];
            v.x = __expf(v.x - mx); v.y = __expf(v.y - mx);
            v.z = __expf(v.z - mx); v.w = __expf(v.w - mx);
            *(float4*)&Sb[q][(lane + t * 32) * 4] = v;
            sum += v.x + v.y + v.z + v.w;
        }
#pragma unroll
        for (int o = 16; o; o >>= 1) sum += __shfl_xor_sync(0xffffffffu, sum, o);
        float inv = 1.f / sum;
        long long base = mrow0 + (long long)q * SS;
#pragma unroll
        for (int t = 0; t < 4; t++) {
            float4 v = *(float4*)&Sb[q][(lane + t * 32) * 4];
            v.x *= inv; v.y *= inv; v.z *= inv; v.w *= inv;
            *(float4*)&Sb[q][(lane + t * 32) * 4] = v;
            __half2 h0 = __floats2half2_rn(v.x, v.y);
            __half2 h1 = __floats2half2_rn(v.z, v.w);
            uint2 packed = { *(unsigned*)&h0, *(unsigned*)&h1 };
            *(uint2*)&attn[base + (lane + t * 32) * 4] = packed;   // 8B aligned
        }
    }

    // ---- attn @ V (2 q-rows per thread; V loads shared) ----
    {
        const int r0 = tid >> 4, dp = tid & 15;   // rows r0 and r0+16
        float2 accA = make_float2(0.f, 0.f), accB = make_float2(0.f, 0.f);
        for (int it = 0; it < 8; it++) {
            const int cur = it & 1;
            const int k0 = it * 64;
            if (it < 7) {
                const float* src = Vb + (size_t)(k0 + 64) * DM;
#pragma unroll
                for (int t = 0; t < 4; t++)
                    cp_async8(&KV2[cur ^ 1][lkk + t * 16][ldp], src + (size_t)(lkk + t * 16) * DM + ldp * 2);
                cp_commit();
            }
            if (it < 7) cp_wait<1>(); else cp_wait<0>();
            __syncthreads();   // at it=0 this also publishes softmax's Sb writes
#pragma unroll
            for (int kp = 0; kp < 32; kp++) {
                float2 apA = *(const float2*)&Sb[r0][k0 + 2 * kp];
                float2 apB = *(const float2*)&Sb[r0 + 16][k0 + 2 * kp];
                float2 v0 = KV2[cur][2 * kp][dp];
                float2 v1 = KV2[cur][2 * kp + 1][dp];
                float2 sA0 = {apA.x, apA.x}, sA1 = {apA.y, apA.y};
                float2 sB0 = {apB.x, apB.x}, sB1 = {apB.y, apB.y};
                ffma2(accA, sA0, v0); ffma2(accA, sA1, v1);
                ffma2(accB, sB0, v0); ffma2(accB, sB1, v1);
            }
            __syncthreads();
        }
        *(float2*)&ctx[((size_t)(b * SS + q0 + r0)) * CTXW + h * DKV + dp * 2] = accA;
        *(float2*)&ctx[((size_t)(b * SS + q0 + r0 + 16)) * CTXW + h * DKV + dp * 2] = accB;
    }
}

// ============================================================
// context2 = matrix @ vp2 -> ctx cols [256, 288).
// ============================================================
__global__ __launch_bounds__(256) void ctx2_kernel(
    const float* __restrict__ matrix, const float* __restrict__ vp2, float* __restrict__ ctx)
{
    __shared__ __align__(16) float  Ms[32][68];
    __shared__ __align__(16) float2 Vs[64][17];
    const int b = blockIdx.y, i0 = blockIdx.x * 32;
    const int tid = threadIdx.x;
    const int r = tid >> 3, cq = tid & 7;

    float2 acc0 = make_float2(0.f, 0.f), acc1 = make_float2(0.f, 0.f);
    for (int k0 = 0; k0 < SS; k0 += 64) {
#pragma unroll
        for (int t = 0; t < 2; t++) {
            int idx = tid + t * 256;
            int row = idx >> 4, c4 = idx & 15;
            *(float4*)&Ms[row][c4 * 4] =
                *(const float4*)&matrix[((size_t)(b * SS + i0 + row)) * SS + k0 + c4 * 4];
        }
#pragma unroll
        for (int t = 0; t < 4; t++) {
            int idx = tid + t * 256, kk = idx >> 4, dp = idx & 15;
            Vs[kk][dp] = *(const float2*)&vp2[((size_t)(b * SS + k0 + kk)) * DKV + dp * 2];
        }
        __syncthreads();
#pragma unroll
        for (int kk = 0; kk < 64; kk++) {
            float a = Ms[r][kk];
            float2 a2 = {a, a};
            ffma2(acc0, a2, Vs[kk][cq * 2]);
            ffma2(acc1, a2, Vs[kk][cq * 2 + 1]);
        }
        __syncthreads();
    }
    float4 o4 = {acc0.x, acc0.y, acc1.x, acc1.y};
    *(float4*)&ctx[((size_t)(b * SS + i0 + r)) * CTXW + HH * DKV + cq * 4] = o4;
}

// ============================================================
// Gate v3: attn read as fp16, MLP-36 batched loads,
// LN -> relu -> sigmoid; matrix_out = matrix * g
// ============================================================
__global__ __launch_bounds__(256) void gate_kernel(
    const __half* __restrict__ attn, const float* __restrict__ matrix, float* __restrict__ mout,
    const float* __restrict__ fu_ln_g, const float* __restrict__ fu_ln_b,
    const float* __restrict__ fu_w1, const float* __restrict__ fu_b1,
    const float* __restrict__ fu_w2, const float* __restrict__ fu_b2)
{
    __shared__ float pl[9][32][33];
    __shared__ float pg[9], pb[9], w1[9][6], b1[6], w2[6], b2s;

    int b = blockIdx.z;
    int i0 = blockIdx.y * 32, j0 = blockIdx.x * 32;
    int tid = threadIdx.x;

    if (tid < 9) { pg[tid] = fu_ln_g[tid]; pb[tid] = fu_ln_b[tid]; }
    if (tid >= 32 && tid < 86) { int t = tid - 32; w1[t / 6][t % 6] = fu_w1[t]; }
    if (tid >= 96 && tid < 102) b1[tid - 96] = fu_b1[tid - 96];
    if (tid >= 128 && tid < 134) w2[tid - 128] = fu_w2[tid - 128];
    if (tid == 160) b2s = fu_b2[0];

    // ---- all loads batched first (1 fp32 plane + 8 fp16 planes x 4 rows) ----
    {
        const int jj0 = tid >> 5, ii = tid & 31;
        const float* msrc = matrix + (size_t)b * SS * SS;
        const __half* asrc[8];
#pragma unroll
        for (int c = 0; c < 8; c++)
            asrc[c] = attn + ((size_t)(b * HH + c)) * SS * SS;

        float  mval[4];
        __half aval[8][4];
#pragma unroll
        for (int t = 0; t < 4; t++)
            mval[t] = msrc[(size_t)(j0 + jj0 + t * 8) * SS + i0 + ii];
#pragma unroll
        for (int c = 0; c < 8; c++)
#pragma unroll
            for (int t = 0; t < 4; t++)
                aval[c][t] = asrc[c][(size_t)(j0 + jj0 + t * 8) * SS + i0 + ii];

#pragma unroll
        for (int t = 0; t < 4; t++)
            pl[0][jj0 + t * 8][ii] = mval[t];
#pragma unroll
        for (int c = 0; c < 8; c++)
#pragma unroll
            for (int t = 0; t < 4; t++)
                pl[c + 1][jj0 + t * 8][ii] = __half2float(aval[c][t]);
    }
    __syncthreads();

#pragma unroll
    for (int r = 0; r < 4; r++) {
        int idx = tid + r * 256;
        int ii = idx >> 5, jj = idx & 31;
        float v[9];
        float m = 0.f;
#pragma unroll
        for (int c = 0; c < 9; c++) { v[c] = pl[c][jj][ii]; m += v[c]; }
        m *= (1.f / 9.f);
        float var = 0.f;
#pragma unroll
        for (int c = 0; c < 9; c++) { float dd = v[c] - m; var += dd * dd; }
        var *= (1.f / 9.f);
        float rinv = rsqrtf(var + EPS);
        float y[9];
#pragma unroll
        for (int c = 0; c < 9; c++) y[c] = pg[c] * (v[c] - m) * rinv + pb[c];
        float z = b2s;
#pragma unroll
        for (int j = 0; j < 6; j++) {
            float t = b1[j];
#pragma unroll
            for (int c = 0; c < 9; c++) t += y[c] * w1[c][j];
            t = fmaxf(t, 0.f);
            z += t * w2[j];
        }
        float g = 1.f / (1.f + __expf(-z));
        long long o = ((long long)b * SS + i0 + ii) * SS + j0 + jj;
        mout[o] = matrix[o] * g;
    }
}

// ============================================================
// Final layernorm over 256 channels: one block per row
// ============================================================
__global__ __launch_bounds__(256) void ln_kernel(
    const float* __restrict__ x, const float* __restrict__ g,
    const float* __restrict__ bt, float* __restrict__ out)
{
    int row = blockIdx.x, tid = threadIdx.x;
    float v = x[(long long)row * DM + tid];

    __shared__ float red[8];
    float s = v;
#pragma unroll
    for (int o = 16; o; o >>= 1) s += __shfl_xor_sync(0xffffffffu, s, o);
    if ((tid & 31) == 0) red[tid >> 5] = s;
    __syncthreads();
    float tot = 0.f;
#pragma unroll
    for (int i = 0; i < 8; i++) tot += red[i];
    float m = tot * (1.f / DM);
    __syncthreads();

    float d = v - m;
    float s2 = d * d;
#pragma unroll
    for (int o = 16; o; o >>= 1) s2 += __shfl_xor_sync(0xffffffffu, s2, o);
    if ((tid & 31) == 0) red[tid >> 5] = s2;
    __syncthreads();
    float vtot = 0.f;
#pragma unroll
    for (int i = 0; i < 8; i++) vtot += red[i];
    float var = vtot * (1.f / DM);

    out[(long long)row * DM + tid] = g[tid] * d * rsqrtf(var + EPS) + bt[tid];
}

// ============================================================
extern "C" void kernel_launch(void* const* d_in, const int* in_sizes, int n_in,
                              void* d_out, int out_size)
{
    const float* inQ    = (const float*)d_in[0];
    const float* inK    = (const float*)d_in[1];
    const float* inV    = (const float*)d_in[2];
    const int*   mask   = (const int*)  d_in[3];
    const float* matrix = (const float*)d_in[4];
    const float* W_Q    = (const float*)d_in[5];
    const float* W_K    = (const float*)d_in[6];
    const float* W_V    = (const float*)d_in[7];
    const float* W_V2   = (const float*)d_in[8];
    const float* W_fc   = (const float*)d_in[9];
    const float* ln_g   = (const float*)d_in[10];
    const float* ln_b   = (const float*)d_in[11];
    const float* fu_ln_g= (const float*)d_in[12];
    const float* fu_ln_b= (const float*)d_in[13];
    const float* fu_w1  = (const float*)d_in[14];
    const float* fu_b1  = (const float*)d_in[15];
    const float* fu_w2  = (const float*)d_in[16];
    const float* fu_b2  = (const float*)d_in[17];

    float* out  = (float*)d_out;                            // [B,S,DM]
    float* mout = (float*)d_out + (long long)BB * SS * DM;  // [B,S,S]

    float *pQ, *pK, *pV, *pvp2, *pctx, *pfc;
    __half* pattn;
    cudaGetSymbolAddress((void**)&pQ, g_Q);
    cudaGetSymbolAddress((void**)&pK, g_K);
    cudaGetSymbolAddress((void**)&pV, g_V);
    cudaGetSymbolAddress((void**)&pattn, g_attn);
    cudaGetSymbolAddress((void**)&pvp2, g_vp2);
    cudaGetSymbolAddress((void**)&pctx, g_ctx);
    cudaGetSymbolAddress((void**)&pfc, g_fc);

    // allow 85 KB dynamic smem for attn5 (host-side attribute; idempotent)
    cudaFuncSetAttribute(attn5_kernel, cudaFuncAttributeMaxDynamicSharedMemorySize, ATTN_SMEM);

    // (0) QKV projections in ONE launch (z-dispatch)
    sgemm2_kernel<<<dim3(4, 64, 3), 256>>>(inQ, inK, inV, W_Q, W_K, W_V,
                                           pQ, pK, pV, DM, DM, DM, DM);
    // (1) vp2 = input_V @ W_V2
    sgemm_n32_kernel<<<dim3(1, 64), 256>>>(inV, W_V2, pvp2, DM, DM);

    // (2) fused attention (32-q tile, 2 q/thread; writes fp16 attn + ctx cols 0..255)
    attn5_kernel<<<dim3(SS / 32, HH, BB), 256, ATTN_SMEM>>>(pQ, pK, pV, mask, pattn, pctx);

    // (3) context2 = matrix @ vp2 -> ctx cols 256..287
    ctx2_kernel<<<dim3(16, BB), 256>>>(matrix, pvp2, pctx);

    // (4) fc: [8192,288] @ [288,256]
    sgemm2_kernel<<<dim3(4, 64, 1), 256>>>(pctx, pctx, pctx, W_fc, W_fc, W_fc,
                                           pfc, pfc, pfc, CTXW, CTXW, DM, DM);

    // (5) gate -> matrix_out
    gate_kernel<<<dim3(SS / 32, SS / 32, BB), 256>>>(pattn, matrix, mout,
                                                     fu_ln_g, fu_ln_b, fu_w1, fu_b1, fu_w2, fu_b2);

    // (6) final layernorm -> output
    ln_kernel<<<BB * SS, 256>>>(pfc, ln_g, ln_b, out);
}

// round 12
// speedup vs baseline: 2.7251x; 1.0639x over previous
#include <cuda_runtime.h>
#include <cuda_fp16.h>
#include <math.h>

// Problem constants
#define BB 16
#define SS 512
#define DM 256
#define HH 8
#define DKV 32
#define CTXW 288   // DV*(H+1)
#define EPS 1e-5f

// -------- scratch (device globals; no allocation allowed) --------
__device__ float  g_Q[BB * SS * DM];
__device__ float  g_K[BB * SS * DM];
__device__ float  g_V[BB * SS * DM];
__device__ __half g_attn[(long)BB * HH * SS * SS];   // 67 MB (fp16)
__device__ float  g_vp2[BB * SS * DKV];
__device__ float  g_ctx[BB * SS * CTXW];
__device__ float  g_fc[BB * SS * DM];

// -------- one-time stream/event setup (load-time ctor: every
// kernel_launch call performs IDENTICAL work; no in-call guards) --------
static cudaStream_t g_s1;
static cudaEvent_t  g_evFork, g_evAttn, g_evCtx2, g_evGate;
namespace {
struct StreamInit {
    StreamInit() {
        cudaStreamCreateWithFlags(&g_s1, cudaStreamNonBlocking);
        cudaEventCreateWithFlags(&g_evFork, cudaEventDisableTiming);
        cudaEventCreateWithFlags(&g_evAttn, cudaEventDisableTiming);
        cudaEventCreateWithFlags(&g_evCtx2, cudaEventDisableTiming);
        cudaEventCreateWithFlags(&g_evGate, cudaEventDisableTiming);
    }
};
StreamInit g_stream_init_;
}

// ---- packed f32x2 FMA (Blackwell FFMA2; PTX-only, ptxas won't auto-fuse) ----
__device__ __forceinline__ void ffma2(float2 &d, const float2 &a, const float2 &b) {
    unsigned long long &dd = reinterpret_cast<unsigned long long &>(d);
    const unsigned long long &aa = reinterpret_cast<const unsigned long long &>(a);
    const unsigned long long &bb = reinterpret_cast<const unsigned long long &>(b);
    asm("fma.rn.f32x2 %0, %1, %2, %0;" : "+l"(dd) : "l"(aa), "l"(bb));
}

// ---- cp.async helpers (8-byte: keeps conflict-free stride-17 smem layout) ----
__device__ __forceinline__ void cp_async8(void* smem, const void* gmem) {
    unsigned saddr = (unsigned)__cvta_generic_to_shared(smem);
    asm volatile("cp.async.ca.shared.global [%0], [%1], 8;" :: "r"(saddr), "l"(gmem));
}
__device__ __forceinline__ void cp_commit() {
    asm volatile("cp.async.commit_group;" ::: "memory");
}
template<int N>
__device__ __forceinline__ void cp_wait() {
    asm volatile("cp.async.wait_group %0;" :: "n"(N) : "memory");
}

// dynamic smem size for attn5: Sb[32][528] f32 + KV2[2][64][17] float2
#define ATTN_SMEM (32 * 528 * 4 + 2 * 64 * 17 * 8)

// ============================================================
// SGEMM v2 (single-buffered inner loop), z-dispatched over up to
// 3 independent (A,B,C) triples. tile 128x64, BK=16, 256 threads.
// ============================================================
__global__ __launch_bounds__(256) void sgemm2_kernel(
    const float* __restrict__ A0, const float* __restrict__ A1, const float* __restrict__ A2,
    const float* __restrict__ B0, const float* __restrict__ B1, const float* __restrict__ B2,
    float* __restrict__ C0, float* __restrict__ C1, float* __restrict__ C2,
    int K, int lda, int ldb, int ldc)
{
    const int z = blockIdx.z;
    const float* A = (z == 0) ? A0 : (z == 1) ? A1 : A2;
    const float* B = (z == 0) ? B0 : (z == 1) ? B1 : B2;
    float*       C = (z == 0) ? C0 : (z == 1) ? C1 : C2;

    __shared__ __align__(16) float As[16][130];  // [k][m], m contiguous
    __shared__ __align__(16) float Bs[16][68];   // [k][n]
    const int tid = threadIdx.x;
    const int tx = tid & 15, ty = tid >> 4;
    const int m0 = blockIdx.y * 128, n0 = blockIdx.x * 64;

    float2 acc[4][4];
#pragma unroll
    for (int i = 0; i < 4; i++)
#pragma unroll
        for (int j = 0; j < 4; j++) acc[i][j] = make_float2(0.f, 0.f);

    for (int k0 = 0; k0 < K; k0 += 16) {
#pragma unroll
        for (int t = 0; t < 2; t++) {
            int idx = tid + t * 256;
            int row = idx >> 2, kq = idx & 3;
            float4 v = *(const float4*)&A[(size_t)(m0 + row) * lda + k0 + kq * 4];
            As[kq * 4 + 0][row] = v.x; As[kq * 4 + 1][row] = v.y;
            As[kq * 4 + 2][row] = v.z; As[kq * 4 + 3][row] = v.w;
        }
        {
            int kk = tid >> 4, nq = tid & 15;
            *(float4*)&Bs[kk][nq * 4] =
                *(const float4*)&B[(size_t)(k0 + kk) * ldb + n0 + nq * 4];
        }
        __syncthreads();
#pragma unroll
        for (int kk = 0; kk < 16; kk++) {
            float2 a[4];
#pragma unroll
            for (int i = 0; i < 4; i++) a[i] = *(float2*)&As[kk][ty * 8 + 2 * i];
            float2 bA = *(float2*)&Bs[kk][tx * 4];
            float2 bB = *(float2*)&Bs[kk][tx * 4 + 2];
            float2 bj[4] = {{bA.x, bA.x}, {bA.y, bA.y}, {bB.x, bB.x}, {bB.y, bB.y}};
#pragma unroll
            for (int j = 0; j < 4; j++)
#pragma unroll
                for (int i = 0; i < 4; i++) ffma2(acc[i][j], a[i], bj[j]);
        }
        __syncthreads();
    }
#pragma unroll
    for (int i = 0; i < 4; i++) {
        int m = m0 + ty * 8 + 2 * i;
        float4 lo = {acc[i][0].x, acc[i][1].x, acc[i][2].x, acc[i][3].x};
        float4 hi = {acc[i][0].y, acc[i][1].y, acc[i][2].y, acc[i][3].y};
        *(float4*)&C[(size_t)m * ldc + n0 + tx * 4] = lo;
        *(float4*)&C[(size_t)(m + 1) * ldc + n0 + tx * 4] = hi;
    }
}

// ============================================================
// SGEMM narrow: N=32 (vp2 projection). tile 128x32, BK=16.
// ============================================================
__global__ __launch_bounds__(256) void sgemm_n32_kernel(
    const float* __restrict__ A, const float* __restrict__ B, float* __restrict__ C,
    int K, int lda)
{
    __shared__ __align__(16) float As[16][130];
    __shared__ __align__(16) float Bs[16][36];
    const int tid = threadIdx.x;
    const int tx = tid & 7, ty = tid >> 3;
    const int m0 = blockIdx.y * 128;

    float2 acc[2][4];
#pragma unroll
    for (int i = 0; i < 2; i++)
#pragma unroll
        for (int j = 0; j < 4; j++) acc[i][j] = make_float2(0.f, 0.f);

    for (int k0 = 0; k0 < K; k0 += 16) {
#pragma unroll
        for (int t = 0; t < 2; t++) {
            int idx = tid + t * 256;
            int row = idx >> 2, kq = idx & 3;
            float4 v = *(const float4*)&A[(size_t)(m0 + row) * lda + k0 + kq * 4];
            As[kq * 4 + 0][row] = v.x; As[kq * 4 + 1][row] = v.y;
            As[kq * 4 + 2][row] = v.z; As[kq * 4 + 3][row] = v.w;
        }
        if (tid < 128) {
            int kk = tid >> 3, nq = tid & 7;
            *(float4*)&Bs[kk][nq * 4] =
                *(const float4*)&B[(size_t)(k0 + kk) * DKV + nq * 4];
        }
        __syncthreads();
#pragma unroll
        for (int kk = 0; kk < 16; kk++) {
            float2 a0 = *(float2*)&As[kk][ty * 4];
            float2 a1 = *(float2*)&As[kk][ty * 4 + 2];
            float2 bA = *(float2*)&Bs[kk][tx * 4];
            float2 bB = *(float2*)&Bs[kk][tx * 4 + 2];
            float2 bj[4] = {{bA.x, bA.x}, {bA.y, bA.y}, {bB.x, bB.x}, {bB.y, bB.y}};
#pragma unroll
            for (int j = 0; j < 4; j++) { ffma2(acc[0][j], a0, bj[j]); ffma2(acc[1][j], a1, bj[j]); }
        }
        __syncthreads();
    }
#pragma unroll
    for (int i = 0; i < 2; i++) {
        int m = m0 + ty * 4 + 2 * i;
        float4 lo = {acc[i][0].x, acc[i][1].x, acc[i][2].x, acc[i][3].x};
        float4 hi = {acc[i][0].y, acc[i][1].y, acc[i][2].y, acc[i][3].y};
        *(float4*)&C[(size_t)m * DKV + tx * 4] = lo;
        *(float4*)&C[(size_t)(m + 1) * DKV + tx * 4] = hi;
    }
}

// ============================================================
// Fused attention v5: 32-q-row tile, 2 q-rows per thread,
// cp.async double-buffered K/V, fp16 attn store. Dynamic smem.
// grid (S/32, H, B), 256 threads.
// ============================================================
__global__ __launch_bounds__(256, 2) void attn5_kernel(
    const float* __restrict__ Q, const float* __restrict__ K, const float* __restrict__ V,
    const int* __restrict__ mask, __half* __restrict__ attn, float* __restrict__ ctx)
{
    extern __shared__ __align__(16) char smem_raw[];
    float  (*Sb)[528]      = reinterpret_cast<float (*)[528]>(smem_raw);             // [32][528]
    float2 (*KV2)[64][17]  = reinterpret_cast<float2 (*)[64][17]>(smem_raw + 32 * 528 * 4); // [2][64][17]

    const int q0 = blockIdx.x * 32;
    const int h = blockIdx.y;
    const int b = blockIdx.z;
    const int tid = threadIdx.x;
    const int lane = tid & 31, warp = tid >> 5;

    const float* Qb = &Q[((size_t)(b * SS + q0)) * DM + h * DKV];
    const float* Kb = &K[((size_t)(b * SS)) * DM + h * DKV];
    const float* Vb = &V[((size_t)(b * SS)) * DM + h * DKV];
    const long long mrow0 = (((long long)(b * HH + h)) * SS + q0) * SS;

    const int lkk = tid >> 4, ldp = tid & 15;   // cp.async loader mapping

    // ---- issue K chunk 0 -> buf 0 immediately ----
#pragma unroll
    for (int t = 0; t < 4; t++)
        cp_async8(&KV2[0][lkk + t * 16][ldp], Kb + (size_t)(lkk + t * 16) * DM + ldp * 2);
    cp_commit();

    // ---- stage scaled Q (32x16 float2) into KV2[1], then to registers ----
    {
        int sq = tid >> 3, dq = tid & 7;
#pragma unroll
        for (int t = 0; t < 2; t++) {
            int dp = dq + t * 8;
            float2 v = *(const float2*)&Qb[(size_t)sq * DM + dp * 2];
            v.x *= 0.17677669529663687f; v.y *= 0.17677669529663687f;
            KV2[1][sq][dp] = v;
        }
    }
    __syncthreads();
    const int p  = (warp << 1) | (lane >> 4);   // 0..15 row-pair id
    const int qA = p, qB = p + 16;
    float2 qrA[16], qrB[16];
#pragma unroll
    for (int dp = 0; dp < 16; dp++) { qrA[dp] = KV2[1][qA][dp]; qrB[dp] = KV2[1][qB][dp]; }
    __syncthreads();   // all Q reads done before it=0 prefetch overwrites buf 1

    // ---- scores + mask (2 q-rows per thread) ----
    const int kb = lane & 15;
    const long long mrowA = mrow0 + (long long)qA * SS;
    const long long mrowB = mrow0 + (long long)qB * SS;
    for (int it = 0; it < 8; it++) {
        const int cur = it & 1;
        const int k0 = it * 64;
        if (it < 7) {
            const float* src = Kb + (size_t)(k0 + 64) * DM;
#pragma unroll
            for (int t = 0; t < 4; t++)
                cp_async8(&KV2[cur ^ 1][lkk + t * 16][ldp], src + (size_t)(lkk + t * 16) * DM + ldp * 2);
            cp_commit();
        }
        int mkA[4], mkB[4];
#pragma unroll
        for (int jj = 0; jj < 4; jj++) {
            mkA[jj] = mask[mrowA + k0 + kb + jj * 16];
            mkB[jj] = mask[mrowB + k0 + kb + jj * 16];
        }
        if (it < 7) cp_wait<1>(); else cp_wait<0>();
        __syncthreads();
#pragma unroll
        for (int jj = 0; jj < 4; jj++) {
            int kk = kb + jj * 16;
            float2 aA = make_float2(0.f, 0.f), aB = make_float2(0.f, 0.f);
#pragma unroll
            for (int dp = 0; dp < 16; dp++) {
                float2 v = KV2[cur][kk][dp];
                ffma2(aA, qrA[dp], v);
                ffma2(aB, qrB[dp], v);
            }
            Sb[qA][k0 + kk] = mkA[jj] ? -1e9f : (aA.x + aA.y);
            Sb[qB][k0 + kk] = mkB[jj] ? -1e9f : (aB.x + aB.y);
        }
        __syncthreads();
    }

    // ---- issue V chunk 0 now: softmax hides its latency ----
#pragma unroll
    for (int t = 0; t < 4; t++)
        cp_async8(&KV2[0][lkk + t * 16][ldp], Vb + (size_t)(lkk + t * 16) * DM + ldp * 2);
    cp_commit();

    // ---- softmax (4 rows per warp) + fp16 attn write ----
#pragma unroll
    for (int rr = 0; rr < 4; rr++) {
        int q = warp * 4 + rr;
        float mx = -1e30f;
#pragma unroll
        for (int t = 0; t < 4; t++) {
            float4 v = *(float4*)&Sb[q][(lane + t * 32) * 4];
            mx = fmaxf(mx, fmaxf(fmaxf(v.x, v.y), fmaxf(v.z, v.w)));
        }
#pragma unroll
        for (int o = 16; o; o >>= 1) mx = fmaxf(mx, __shfl_xor_sync(0xffffffffu, mx, o));
        float sum = 0.f;
#pragma unroll
        for (int t = 0; t < 4; t++) {
            float4 v = *(float4*)&Sb[q][(lane + t * 32) * 4];
            v.x = __expf(v.x - mx); v.y = __expf(v.y - mx);
            v.z = __expf(v.z - mx); v.w = __expf(v.w - mx);
            *(float4*)&Sb[q][(lane + t * 32) * 4] = v;
            sum += v.x + v.y + v.z + v.w;
        }
#pragma unroll
        for (int o = 16; o; o >>= 1) sum += __shfl_xor_sync(0xffffffffu, sum, o);
        float inv = 1.f / sum;
        long long base = mrow0 + (long long)q * SS;
#pragma unroll
        for (int t = 0; t < 4; t++) {
            float4 v = *(float4*)&Sb[q][(lane + t * 32) * 4];
            v.x *= inv; v.y *= inv; v.z *= inv; v.w *= inv;
            *(float4*)&Sb[q][(lane + t * 32) * 4] = v;
            __half2 h0 = __floats2half2_rn(v.x, v.y);
            __half2 h1 = __floats2half2_rn(v.z, v.w);
            uint2 packed = { *(unsigned*)&h0, *(unsigned*)&h1 };
            *(uint2*)&attn[base + (lane + t * 32) * 4] = packed;   // 8B aligned
        }
    }

    // ---- attn @ V (2 q-rows per thread; V loads shared) ----
    {
        const int r0 = tid >> 4, dp = tid & 15;   // rows r0 and r0+16
        float2 accA = make_float2(0.f, 0.f), accB = make_float2(0.f, 0.f);
        for (int it = 0; it < 8; it++) {
            const int cur = it & 1;
            const int k0 = it * 64;
            if (it < 7) {
                const float* src = Vb + (size_t)(k0 + 64) * DM;
#pragma unroll
                for (int t = 0; t < 4; t++)
                    cp_async8(&KV2[cur ^ 1][lkk + t * 16][ldp], src + (size_t)(lkk + t * 16) * DM + ldp * 2);
                cp_commit();
            }
            if (it < 7) cp_wait<1>(); else cp_wait<0>();
            __syncthreads();   // at it=0 this also publishes softmax's Sb writes
#pragma unroll
            for (int kp = 0; kp < 32; kp++) {
                float2 apA = *(const float2*)&Sb[r0][k0 + 2 * kp];
                float2 apB = *(const float2*)&Sb[r0 + 16][k0 + 2 * kp];
                float2 v0 = KV2[cur][2 * kp][dp];
                float2 v1 = KV2[cur][2 * kp + 1][dp];
                float2 sA0 = {apA.x, apA.x}, sA1 = {apA.y, apA.y};
                float2 sB0 = {apB.x, apB.x}, sB1 = {apB.y, apB.y};
                ffma2(accA, sA0, v0); ffma2(accA, sA1, v1);
                ffma2(accB, sB0, v0); ffma2(accB, sB1, v1);
            }
            __syncthreads();
        }
        *(float2*)&ctx[((size_t)(b * SS + q0 + r0)) * CTXW + h * DKV + dp * 2] = accA;
        *(float2*)&ctx[((size_t)(b * SS + q0 + r0 + 16)) * CTXW + h * DKV + dp * 2] = accB;
    }
}

// ============================================================
// context2 = matrix @ vp2 -> ctx cols [256, 288).
// ============================================================
__global__ __launch_bounds__(256) void ctx2_kernel(
    const float* __restrict__ matrix, const float* __restrict__ vp2, float* __restrict__ ctx)
{
    __shared__ __align__(16) float  Ms[32][68];
    __shared__ __align__(16) float2 Vs[64][17];
    const int b = blockIdx.y, i0 = blockIdx.x * 32;
    const int tid = threadIdx.x;
    const int r = tid >> 3, cq = tid & 7;

    float2 acc0 = make_float2(0.f, 0.f), acc1 = make_float2(0.f, 0.f);
    for (int k0 = 0; k0 < SS; k0 += 64) {
#pragma unroll
        for (int t = 0; t < 2; t++) {
            int idx = tid + t * 256;
            int row = idx >> 4, c4 = idx & 15;
            *(float4*)&Ms[row][c4 * 4] =
                *(const float4*)&matrix[((size_t)(b * SS + i0 + row)) * SS + k0 + c4 * 4];
        }
#pragma unroll
        for (int t = 0; t < 4; t++) {
            int idx = tid + t * 256, kk = idx >> 4, dp = idx & 15;
            Vs[kk][dp] = *(const float2*)&vp2[((size_t)(b * SS + k0 + kk)) * DKV + dp * 2];
        }
        __syncthreads();
#pragma unroll
        for (int kk = 0; kk < 64; kk++) {
            float a = Ms[r][kk];
            float2 a2 = {a, a};
            ffma2(acc0, a2, Vs[kk][cq * 2]);
            ffma2(acc1, a2, Vs[kk][cq * 2 + 1]);
        }
        __syncthreads();
    }
    float4 o4 = {acc0.x, acc0.y, acc1.x, acc1.y};
    *(float4*)&ctx[((size_t)(b * SS + i0 + r)) * CTXW + HH * DKV + cq * 4] = o4;
}

// ============================================================
// Gate v3: attn read as fp16, MLP-36 batched loads,
// LN -> relu -> sigmoid; matrix_out = matrix * g
// ============================================================
__global__ __launch_bounds__(256) void gate_kernel(
    const __half* __restrict__ attn, const float* __restrict__ matrix, float* __restrict__ mout,
    const float* __restrict__ fu_ln_g, const float* __restrict__ fu_ln_b,
    const float* __restrict__ fu_w1, const float* __restrict__ fu_b1,
    const float* __restrict__ fu_w2, const float* __restrict__ fu_b2)
{
    __shared__ float pl[9][32][33];
    __shared__ float pg[9], pb[9], w1[9][6], b1[6], w2[6], b2s;

    int b = blockIdx.z;
    int i0 = blockIdx.y * 32, j0 = blockIdx.x * 32;
    int tid = threadIdx.x;

    if (tid < 9) { pg[tid] = fu_ln_g[tid]; pb[tid] = fu_ln_b[tid]; }
    if (tid >= 32 && tid < 86) { int t = tid - 32; w1[t / 6][t % 6] = fu_w1[t]; }
    if (tid >= 96 && tid < 102) b1[tid - 96] = fu_b1[tid - 96];
    if (tid >= 128 && tid < 134) w2[tid - 128] = fu_w2[tid - 128];
    if (tid == 160) b2s = fu_b2[0];

    // ---- all loads batched first (1 fp32 plane + 8 fp16 planes x 4 rows) ----
    {
        const int jj0 = tid >> 5, ii = tid & 31;
        const float* msrc = matrix + (size_t)b * SS * SS;
        const __half* asrc[8];
#pragma unroll
        for (int c = 0; c < 8; c++)
            asrc[c] = attn + ((size_t)(b * HH + c)) * SS * SS;

        float  mval[4];
        __half aval[8][4];
#pragma unroll
        for (int t = 0; t < 4; t++)
            mval[t] = msrc[(size_t)(j0 + jj0 + t * 8) * SS + i0 + ii];
#pragma unroll
        for (int c = 0; c < 8; c++)
#pragma unroll
            for (int t = 0; t < 4; t++)
                aval[c][t] = asrc[c][(size_t)(j0 + jj0 + t * 8) * SS + i0 + ii];

#pragma unroll
        for (int t = 0; t < 4; t++)
            pl[0][jj0 + t * 8][ii] = mval[t];
#pragma unroll
        for (int c = 0; c < 8; c++)
#pragma unroll
            for (int t = 0; t < 4; t++)
                pl[c + 1][jj0 + t * 8][ii] = __half2float(aval[c][t]);
    }
    __syncthreads();

#pragma unroll
    for (int r = 0; r < 4; r++) {
        int idx = tid + r * 256;
        int ii = idx >> 5, jj = idx & 31;
        float v[9];
        float m = 0.f;
#pragma unroll
        for (int c = 0; c < 9; c++) { v[c] = pl[c][jj][ii]; m += v[c]; }
        m *= (1.f / 9.f);
        float var = 0.f;
#pragma unroll
        for (int c = 0; c < 9; c++) { float dd = v[c] - m; var += dd * dd; }
        var *= (1.f / 9.f);
        float rinv = rsqrtf(var + EPS);
        float y[9];
#pragma unroll
        for (int c = 0; c < 9; c++) y[c] = pg[c] * (v[c] - m) * rinv + pb[c];
        float z = b2s;
#pragma unroll
        for (int j = 0; j < 6; j++) {
            float t = b1[j];
#pragma unroll
            for (int c = 0; c < 9; c++) t += y[c] * w1[c][j];
            t = fmaxf(t, 0.f);
            z += t * w2[j];
        }
        float g = 1.f / (1.f + __expf(-z));
        long long o = ((long long)b * SS + i0 + ii) * SS + j0 + jj;
        mout[o] = matrix[o] * g;
    }
}

// ============================================================
// Final layernorm over 256 channels: one block per row
// ============================================================
__global__ __launch_bounds__(256) void ln_kernel(
    const float* __restrict__ x, const float* __restrict__ g,
    const float* __restrict__ bt, float* __restrict__ out)
{
    int row = blockIdx.x, tid = threadIdx.x;
    float v = x[(long long)row * DM + tid];

    __shared__ float red[8];
    float s = v;
#pragma unroll
    for (int o = 16; o; o >>= 1) s += __shfl_xor_sync(0xffffffffu, s, o);
    if ((tid & 31) == 0) red[tid >> 5] = s;
    __syncthreads();
    float tot = 0.f;
#pragma unroll
    for (int i = 0; i < 8; i++) tot += red[i];
    float m = tot * (1.f / DM);
    __syncthreads();

    float d = v - m;
    float s2 = d * d;
#pragma unroll
    for (int o = 16; o; o >>= 1) s2 += __shfl_xor_sync(0xffffffffu, s2, o);
    if ((tid & 31) == 0) red[tid >> 5] = s2;
    __syncthreads();
    float vtot = 0.f;
#pragma unroll
    for (int i = 0; i < 8; i++) vtot += red[i];
    float var = vtot * (1.f / DM);

    out[(long long)row * DM + tid] = g[tid] * d * rsqrtf(var + EPS) + bt[tid];
}

// ============================================================
extern "C" void kernel_launch(void* const* d_in, const int* in_sizes, int n_in,
                              void* d_out, int out_size)
{
    const float* inQ    = (const float*)d_in[0];
    const float* inK    = (const float*)d_in[1];
    const float* inV    = (const float*)d_in[2];
    const int*   mask   = (const int*)  d_in[3];
    const float* matrix = (const float*)d_in[4];
    const float* W_Q    = (const float*)d_in[5];
    const float* W_K    = (const float*)d_in[6];
    const float* W_V    = (const float*)d_in[7];
    const float* W_V2   = (const float*)d_in[8];
    const float* W_fc   = (const float*)d_in[9];
    const float* ln_g   = (const float*)d_in[10];
    const float* ln_b   = (const float*)d_in[11];
    const float* fu_ln_g= (const float*)d_in[12];
    const float* fu_ln_b= (const float*)d_in[13];
    const float* fu_w1  = (const float*)d_in[14];
    const float* fu_b1  = (const float*)d_in[15];
    const float* fu_w2  = (const float*)d_in[16];
    const float* fu_b2  = (const float*)d_in[17];

    float* out  = (float*)d_out;                            // [B,S,DM]
    float* mout = (float*)d_out + (long long)BB * SS * DM;  // [B,S,S]

    float *pQ, *pK, *pV, *pvp2, *pctx, *pfc;
    __half* pattn;
    cudaGetSymbolAddress((void**)&pQ, g_Q);
    cudaGetSymbolAddress((void**)&pK, g_K);
    cudaGetSymbolAddress((void**)&pV, g_V);
    cudaGetSymbolAddress((void**)&pattn, g_attn);
    cudaGetSymbolAddress((void**)&pvp2, g_vp2);
    cudaGetSymbolAddress((void**)&pctx, g_ctx);
    cudaGetSymbolAddress((void**)&pfc, g_fc);

    cudaFuncSetAttribute(attn5_kernel, cudaFuncAttributeMaxDynamicSharedMemorySize, ATTN_SMEM);

    // ---- fork side stream s1 from the main (capture) stream ----
    cudaEventRecord(g_evFork, 0);
    cudaStreamWaitEvent(g_s1, g_evFork, 0);

    // main: QKV projections -> attention
    sgemm2_kernel<<<dim3(4, 64, 3), 256>>>(inQ, inK, inV, W_Q, W_K, W_V,
                                           pQ, pK, pV, DM, DM, DM, DM);
    attn5_kernel<<<dim3(SS / 32, HH, BB), 256, ATTN_SMEM>>>(pQ, pK, pV, mask, pattn, pctx);
    cudaEventRecord(g_evAttn, 0);

    // s1 (parallel with QKV+attn): vp2 -> ctx2
    sgemm_n32_kernel<<<dim3(1, 64), 256, 0, g_s1>>>(inV, W_V2, pvp2, DM, DM);
    ctx2_kernel<<<dim3(16, BB), 256, 0, g_s1>>>(matrix, pvp2, pctx);
    cudaEventRecord(g_evCtx2, g_s1);

    // s1: gate needs attn -> wait, then run (parallel with fc+ln on main)
    cudaStreamWaitEvent(g_s1, g_evAttn, 0);
    gate_kernel<<<dim3(SS / 32, SS / 32, BB), 256, 0, g_s1>>>(pattn, matrix, mout,
                                                     fu_ln_g, fu_ln_b, fu_w1, fu_b1, fu_w2, fu_b2);
    cudaEventRecord(g_evGate, g_s1);

    // main: fc needs ctx2 (and attn, already ordered) -> wait, then fc + ln
    cudaStreamWaitEvent(0, g_evCtx2, 0);
    sgemm2_kernel<<<dim3(4, 64, 1), 256>>>(pctx, pctx, pctx, W_fc, W_fc, W_fc,
                                           pfc, pfc, pfc, CTXW, CTXW, DM, DM);
    ln_kernel<<<BB * SS, 256>>>(pfc, ln_g, ln_b, out);

    // join: gate must complete before the graph ends
    cudaStreamWaitEvent(0, g_evGate, 0);
}